// round 1
// baseline (speedup 1.0000x reference)
#include <cuda_runtime.h>
#include <math.h>

// ===== Model config =====
#define B_   8
#define C_   3
#define H_   384
#define W_   384
#define P_   16
#define GH_  24
#define GW_  24
#define NP_  576
#define N_   577
#define D_   768
#define NH_  12
#define HD_  64
#define MLP_ 3072
#define L_   12
#define NCLS_ 1000

#define MROWS (B_*N_)        // 4616
#define PROWS (B_*NP_)       // 4608

// ===== Scratch (static device globals; allocation-free at launch time) =====
__device__ float g_t[B_*NP_*D_];                    // patchified input  [4608,768]
__device__ float g_h[MROWS*D_];                     // residual stream
__device__ float g_y[MROWS*D_];                     // LN output / emb scratch
__device__ float g_q[MROWS*D_];
__device__ float g_k[MROWS*D_];
__device__ float g_v[MROWS*D_];
__device__ float g_o[MROWS*D_];                     // attention output
__device__ float g_m[MROWS*MLP_];                   // MLP hidden
__device__ float g_s[(size_t)B_*NH_*N_*N_];         // attention scores [96,577,577]

// ===== Patchify (replicates the reference's exact flatten order incl. batch mixing) =====
// linear index over t (== element count of x); p1-major blocks of 221184
__global__ void patchify_kernel(const float* __restrict__ x) {
    int idx = blockIdx.x * blockDim.x + threadIdx.x;
    if (idx >= B_*NP_*D_) return;
    const int BLK = B_*C_*GH_*GW_*P_;   // 221184
    int p1 = idx / BLK;
    int r  = idx % BLK;
    int m  = r >> 4;
    int p2 = r & 15;
    int gw = m % GW_;  int m2 = m / GW_;
    int gh = m2 % GH_; int m3 = m2 / GH_;
    int c  = m3 % C_;  int bx = m3 / C_;
    g_t[idx] = x[(((size_t)(bx*C_ + c)*H_) + gh*P_ + p1)*W_ + gw*P_ + p2];
}

// ===== Assemble h = concat(cls, emb) + pos =====
__global__ void assemble_kernel(const float* __restrict__ cls, const float* __restrict__ pos) {
    int idx = blockIdx.x * blockDim.x + threadIdx.x;
    if (idx >= MROWS*D_) return;
    int d  = idx % D_;
    int rn = idx / D_;
    int n  = rn % N_;
    int b  = rn / N_;
    float v = (n == 0) ? cls[d] : g_y[((size_t)(b*NP_ + n - 1))*D_ + d];
    g_h[idx] = v + pos[n*D_ + d];
}

// ===== LayerNorm: one block per row of 768 =====
__global__ void ln_kernel(const float* __restrict__ in, float* __restrict__ out,
                          const float* __restrict__ g, const float* __restrict__ bb) {
    __shared__ float red[256];
    int row = blockIdx.x;
    int tid = threadIdx.x;
    const float* p = in + (size_t)row * D_;
    float s = 0.f;
    for (int c = tid; c < D_; c += 256) s += p[c];
    red[tid] = s; __syncthreads();
    for (int st = 128; st > 0; st >>= 1) { if (tid < st) red[tid] += red[tid+st]; __syncthreads(); }
    float mean = red[0] * (1.0f / D_);
    __syncthreads();
    float vs = 0.f;
    for (int c = tid; c < D_; c += 256) { float dx = p[c]-mean; vs += dx*dx; }
    red[tid] = vs; __syncthreads();
    for (int st = 128; st > 0; st >>= 1) { if (tid < st) red[tid] += red[tid+st]; __syncthreads(); }
    float rs = rsqrtf(red[0] * (1.0f / D_) + 1e-5f);
    float* q = out + (size_t)row * D_;
    for (int c = tid; c < D_; c += 256) q[c] = (p[c]-mean)*rs*g[c] + bb[c];
}

// ===== Generic SGEMM: C[M,Nc] = epi(A[M,K] @ W[K,Nc] + bias)  =====
// EPI 0: +bias    EPI 1: +bias+res (residual)    EPI 2: gelu(+bias)
#define TS 64
#define KS 16
template<int EPI>
__global__ __launch_bounds__(256) void sgemm_kernel(
        const float* __restrict__ A, const float* __restrict__ W,
        const float* __restrict__ bias, const float* __restrict__ res,
        float* __restrict__ C, int M, int Nc, int K) {
    __shared__ float As[KS][TS+4];   // +4 floats keeps float4 alignment, kills conflicts
    __shared__ float Ws[KS][TS+4];
    int tx = threadIdx.x, ty = threadIdx.y;
    int tid = ty*16 + tx;
    int row0 = blockIdx.y * TS;
    int col0 = blockIdx.x * TS;
    float acc[4][4] = {};
    for (int kt = 0; kt < K; kt += KS) {
        #pragma unroll
        for (int l = 0; l < 4; l++) {
            int idx = tid + l*256;          // 0..1023
            int m  = idx >> 4;
            int kk = idx & 15;
            int gr = row0 + m;
            As[kk][m] = (gr < M) ? A[(size_t)gr*K + kt + kk] : 0.f;
        }
        #pragma unroll
        for (int l = 0; l < 4; l++) {
            int idx = tid + l*256;
            int kk = idx >> 6;
            int n  = idx & 63;
            int gc = col0 + n;
            Ws[kk][n] = (gc < Nc) ? W[(size_t)(kt+kk)*Nc + gc] : 0.f;
        }
        __syncthreads();
        #pragma unroll
        for (int kk = 0; kk < KS; kk++) {
            float4 a4 = *reinterpret_cast<const float4*>(&As[kk][ty*4]);
            float4 b4 = *reinterpret_cast<const float4*>(&Ws[kk][tx*4]);
            float a[4] = {a4.x, a4.y, a4.z, a4.w};
            float bv[4] = {b4.x, b4.y, b4.z, b4.w};
            #pragma unroll
            for (int i = 0; i < 4; i++)
                #pragma unroll
                for (int j = 0; j < 4; j++)
                    acc[i][j] = fmaf(a[i], bv[j], acc[i][j]);
        }
        __syncthreads();
    }
    #pragma unroll
    for (int i = 0; i < 4; i++) {
        int r = row0 + ty*4 + i;
        if (r >= M) continue;
        #pragma unroll
        for (int j = 0; j < 4; j++) {
            int cc = col0 + tx*4 + j;
            if (cc >= Nc) continue;
            float v = acc[i][j] + bias[cc];
            if (EPI == 1) v += res[(size_t)r*Nc + cc];
            if (EPI == 2) v = 0.5f * v * (1.0f + erff(v * 0.70710678118654752f));
            C[(size_t)r*Nc + cc] = v;
        }
    }
}

// ===== Attention scores: S[z,i,j] = scale * q[b,i,h,:] . k[b,j,h,:] =====
__global__ __launch_bounds__(256) void attn_score_kernel(
        const float* __restrict__ q, const float* __restrict__ k, float* __restrict__ s) {
    __shared__ float Qs[32][HD_+1];
    __shared__ float Ks[32][HD_+1];
    int z = blockIdx.z;
    int b = z / NH_, h = z % NH_;
    int i0 = blockIdx.y * 32, j0 = blockIdx.x * 32;
    int tx = threadIdx.x, ty = threadIdx.y;
    int tid = ty*16 + tx;
    #pragma unroll
    for (int l = 0; l < 8; l++) {
        int idx = tid + l*256;
        int r = idx >> 6, d = idx & 63;
        int gi = i0 + r;
        Qs[r][d] = (gi < N_) ? q[((size_t)(b*N_ + gi))*D_ + h*HD_ + d] : 0.f;
        int gj = j0 + r;
        Ks[r][d] = (gj < N_) ? k[((size_t)(b*N_ + gj))*D_ + h*HD_ + d] : 0.f;
    }
    __syncthreads();
    float acc[2][2] = {};
    #pragma unroll
    for (int d = 0; d < HD_; d++) {
        float a0 = Qs[ty][d],    a1 = Qs[ty+16][d];
        float b0 = Ks[tx][d],    b1 = Ks[tx+16][d];
        acc[0][0] = fmaf(a0, b0, acc[0][0]);
        acc[0][1] = fmaf(a0, b1, acc[0][1]);
        acc[1][0] = fmaf(a1, b0, acc[1][0]);
        acc[1][1] = fmaf(a1, b1, acc[1][1]);
    }
    #pragma unroll
    for (int ii = 0; ii < 2; ii++) {
        int i = i0 + ty + 16*ii;
        if (i >= N_) continue;
        #pragma unroll
        for (int jj = 0; jj < 2; jj++) {
            int j = j0 + tx + 16*jj;
            if (j >= N_) continue;
            s[((size_t)z*N_ + i)*N_ + j] = acc[ii][jj] * 0.125f;
        }
    }
}

// ===== Softmax over j (577) — one block per row =====
__global__ void softmax_kernel(float* __restrict__ s) {
    __shared__ float red[256];
    int row = blockIdx.x;
    float* p = s + (size_t)row * N_;
    int tid = threadIdx.x;
    float mx = -1e30f;
    for (int c = tid; c < N_; c += 256) mx = fmaxf(mx, p[c]);
    red[tid] = mx; __syncthreads();
    for (int st = 128; st > 0; st >>= 1) { if (tid < st) red[tid] = fmaxf(red[tid], red[tid+st]); __syncthreads(); }
    mx = red[0]; __syncthreads();
    float sum = 0.f;
    for (int c = tid; c < N_; c += 256) { float e = __expf(p[c]-mx); p[c] = e; sum += e; }
    red[tid] = sum; __syncthreads();
    for (int st = 128; st > 0; st >>= 1) { if (tid < st) red[tid] += red[tid+st]; __syncthreads(); }
    float inv = 1.0f / red[0];
    for (int c = tid; c < N_; c += 256) p[c] *= inv;
}

// ===== O = S @ V per (b,h): [577,577]x[577,64] -> write to [B,N,D] =====
__global__ __launch_bounds__(256) void attn_av_kernel(
        const float* __restrict__ s, const float* __restrict__ v, float* __restrict__ o) {
    __shared__ float Ss[32][33];
    __shared__ float Vs[32][HD_+1];
    int z = blockIdx.y;
    int b = z / NH_, h = z % NH_;
    int i0 = blockIdx.x * 32;
    int tx = threadIdx.x, ty = threadIdx.y;
    int tid = ty*16 + tx;
    float acc[2][4] = {};
    for (int jt = 0; jt < N_; jt += 32) {
        #pragma unroll
        for (int l = 0; l < 4; l++) {
            int idx = tid + l*256;
            int il = idx >> 5, jl = idx & 31;
            int gi = i0 + il, gj = jt + jl;
            Ss[il][jl] = (gi < N_ && gj < N_) ? s[((size_t)z*N_ + gi)*N_ + gj] : 0.f;
        }
        #pragma unroll
        for (int l = 0; l < 8; l++) {
            int idx = tid + l*256;
            int jl = idx >> 6, d = idx & 63;
            int gj = jt + jl;
            Vs[jl][d] = (gj < N_) ? v[((size_t)(b*N_ + gj))*D_ + h*HD_ + d] : 0.f;
        }
        __syncthreads();
        #pragma unroll
        for (int kk = 0; kk < 32; kk++) {
            float a0 = Ss[ty][kk], a1 = Ss[ty+16][kk];
            float bv[4];
            #pragma unroll
            for (int jj = 0; jj < 4; jj++) bv[jj] = Vs[kk][tx + 16*jj];
            #pragma unroll
            for (int jj = 0; jj < 4; jj++) {
                acc[0][jj] = fmaf(a0, bv[jj], acc[0][jj]);
                acc[1][jj] = fmaf(a1, bv[jj], acc[1][jj]);
            }
        }
        __syncthreads();
    }
    #pragma unroll
    for (int ii = 0; ii < 2; ii++) {
        int i = i0 + ty + 16*ii;
        if (i >= N_) continue;
        #pragma unroll
        for (int jj = 0; jj < 4; jj++) {
            int d = tx + 16*jj;
            o[((size_t)(b*N_ + i))*D_ + h*HD_ + d] = acc[ii][jj];
        }
    }
}

// ===== Head: logits[b,c] = LN(h)[b,0,:] @ head_w + head_b =====
__global__ void head_kernel(const float* __restrict__ y, const float* __restrict__ hw,
                            const float* __restrict__ hb, float* __restrict__ out) {
    __shared__ float rowv[D_];
    int b = blockIdx.x;
    int tid = threadIdx.x;
    for (int c = tid; c < D_; c += 256) rowv[c] = y[((size_t)(b*N_))*D_ + c];
    __syncthreads();
    for (int c = tid; c < NCLS_; c += 256) {
        float s = hb[c];
        for (int d = 0; d < D_; d++) s = fmaf(rowv[d], hw[(size_t)d*NCLS_ + c], s);
        out[b*NCLS_ + c] = s;
    }
}

extern "C" void kernel_launch(void* const* d_in, const int* in_sizes, int n_in,
                              void* d_out, int out_size) {
    (void)in_sizes; (void)n_in; (void)out_size;
    const float* x       = (const float*)d_in[0];
    const float* proj_w  = (const float*)d_in[1];
    const float* proj_b  = (const float*)d_in[2];
    const float* cls_emb = (const float*)d_in[3];
    const float* pos_emb = (const float*)d_in[4];
    const float* ln1_g   = (const float*)d_in[5];
    const float* ln1_b   = (const float*)d_in[6];
    const float* qw = (const float*)d_in[7];
    const float* qb = (const float*)d_in[8];
    const float* kw = (const float*)d_in[9];
    const float* kb = (const float*)d_in[10];
    const float* vw = (const float*)d_in[11];
    const float* vb = (const float*)d_in[12];
    const float* ow = (const float*)d_in[13];
    const float* ob = (const float*)d_in[14];
    const float* ln2_g = (const float*)d_in[15];
    const float* ln2_b = (const float*)d_in[16];
    const float* fcw = (const float*)d_in[17];
    const float* fcb = (const float*)d_in[18];
    const float* pw  = (const float*)d_in[19];
    const float* pb  = (const float*)d_in[20];
    const float* lnf_g = (const float*)d_in[21];
    const float* lnf_b = (const float*)d_in[22];
    const float* head_w = (const float*)d_in[23];
    const float* head_b = (const float*)d_in[24];
    float* out = (float*)d_out;

    float *t_p, *h_p, *y_p, *q_p, *k_p, *v_p, *o_p, *m_p, *s_p;
    cudaGetSymbolAddress((void**)&t_p, g_t);
    cudaGetSymbolAddress((void**)&h_p, g_h);
    cudaGetSymbolAddress((void**)&y_p, g_y);
    cudaGetSymbolAddress((void**)&q_p, g_q);
    cudaGetSymbolAddress((void**)&k_p, g_k);
    cudaGetSymbolAddress((void**)&v_p, g_v);
    cudaGetSymbolAddress((void**)&o_p, g_o);
    cudaGetSymbolAddress((void**)&m_p, g_m);
    cudaGetSymbolAddress((void**)&s_p, g_s);

    dim3 tb(16, 16);

    // Patch embed
    patchify_kernel<<<(B_*NP_*D_ + 255)/256, 256>>>(x);
    sgemm_kernel<0><<<dim3((D_+TS-1)/TS, (PROWS+TS-1)/TS), tb>>>(
        t_p, proj_w, proj_b, nullptr, y_p, PROWS, D_, D_);
    assemble_kernel<<<(MROWS*D_ + 255)/256, 256>>>(cls_emb, pos_emb);

    const int gN_D   = (D_   + TS - 1) / TS;   // 12
    const int gN_MLP = (MLP_ + TS - 1) / TS;   // 48
    const int gM     = (MROWS + TS - 1) / TS;  // 73
    const int nTile  = (N_ + 31) / 32;         // 19

    for (int l = 0; l < L_; l++) {
        const float* qw_l = qw + (size_t)l*D_*D_;
        const float* kw_l = kw + (size_t)l*D_*D_;
        const float* vw_l = vw + (size_t)l*D_*D_;
        const float* ow_l = ow + (size_t)l*D_*D_;
        const float* fcw_l = fcw + (size_t)l*D_*MLP_;
        const float* pw_l  = pw  + (size_t)l*MLP_*D_;

        ln_kernel<<<MROWS, 256>>>(h_p, y_p, ln1_g + l*D_, ln1_b + l*D_);
        sgemm_kernel<0><<<dim3(gN_D, gM), tb>>>(y_p, qw_l, qb + l*D_, nullptr, q_p, MROWS, D_, D_);
        sgemm_kernel<0><<<dim3(gN_D, gM), tb>>>(y_p, kw_l, kb + l*D_, nullptr, k_p, MROWS, D_, D_);
        sgemm_kernel<0><<<dim3(gN_D, gM), tb>>>(y_p, vw_l, vb + l*D_, nullptr, v_p, MROWS, D_, D_);

        attn_score_kernel<<<dim3(nTile, nTile, B_*NH_), tb>>>(q_p, k_p, s_p);
        softmax_kernel<<<B_*NH_*N_, 256>>>(s_p);
        attn_av_kernel<<<dim3(nTile, B_*NH_), tb>>>(s_p, v_p, o_p);

        sgemm_kernel<1><<<dim3(gN_D, gM), tb>>>(o_p, ow_l, ob + l*D_, h_p, h_p, MROWS, D_, D_);

        ln_kernel<<<MROWS, 256>>>(h_p, y_p, ln2_g + l*D_, ln2_b + l*D_);
        sgemm_kernel<2><<<dim3(gN_MLP, gM), tb>>>(y_p, fcw_l, fcb + l*MLP_, nullptr, m_p, MROWS, MLP_, D_);
        sgemm_kernel<1><<<dim3(gN_D, gM), tb>>>(m_p, pw_l, pb + l*D_, h_p, h_p, MROWS, D_, MLP_);
    }

    ln_kernel<<<MROWS, 256>>>(h_p, y_p, lnf_g, lnf_b);
    head_kernel<<<B_, 256>>>(y_p, head_w, head_b, out);
}

// round 2
// speedup vs baseline: 3.3131x; 3.3131x over previous
#include <cuda_runtime.h>
#include <math.h>

// ===== Model config =====
#define B_   8
#define C_   3
#define H_   384
#define W_   384
#define P_   16
#define GH_  24
#define GW_  24
#define NP_  576
#define N_   577
#define D_   768
#define NH_  12
#define HD_  64
#define MLP_ 3072
#define L_   12
#define NCLS_ 1000

#define MROWS (B_*N_)        // 4616
#define PROWS (B_*NP_)       // 4608

// ===== Scratch =====
__device__ float g_t[B_*NP_*D_];
__device__ float g_h[MROWS*D_];
__device__ float g_y[MROWS*D_];
__device__ float g_q[MROWS*D_];
__device__ float g_k[MROWS*D_];
__device__ float g_v[MROWS*D_];
__device__ float g_o[MROWS*D_];
__device__ float g_m[MROWS*MLP_];
__device__ float g_s[(size_t)B_*NH_*N_*N_];

__device__ __forceinline__ unsigned f2tf(float f) {
    unsigned u;
    asm("cvt.rna.tf32.f32 %0, %1;" : "=r"(u) : "f"(f));
    return u;
}

// ===== Patchify (exact reference flatten order) =====
__global__ void patchify_kernel(const float* __restrict__ x) {
    int idx = blockIdx.x * blockDim.x + threadIdx.x;
    if (idx >= B_*NP_*D_) return;
    const int BLK = B_*C_*GH_*GW_*P_;   // 221184
    int p1 = idx / BLK;
    int r  = idx % BLK;
    int m  = r >> 4;
    int p2 = r & 15;
    int gw = m % GW_;  int m2 = m / GW_;
    int gh = m2 % GH_; int m3 = m2 / GH_;
    int c  = m3 % C_;  int bx = m3 / C_;
    g_t[idx] = x[(((size_t)(bx*C_ + c)*H_) + gh*P_ + p1)*W_ + gw*P_ + p2];
}

// ===== Assemble h = concat(cls, emb) + pos =====
__global__ void assemble_kernel(const float* __restrict__ cls, const float* __restrict__ pos) {
    int idx = blockIdx.x * blockDim.x + threadIdx.x;
    if (idx >= MROWS*D_) return;
    int d  = idx % D_;
    int rn = idx / D_;
    int n  = rn % N_;
    int b  = rn / N_;
    float v = (n == 0) ? cls[d] : g_y[((size_t)(b*NP_ + n - 1))*D_ + d];
    g_h[idx] = v + pos[n*D_ + d];
}

// ===== LayerNorm: warp per row (768 = 24*32) =====
__global__ __launch_bounds__(256) void ln_kernel(const float* __restrict__ in, float* __restrict__ out,
                          const float* __restrict__ g, const float* __restrict__ bb) {
    int wid = threadIdx.x >> 5, lane = threadIdx.x & 31;
    int row = blockIdx.x * 8 + wid;
    if (row >= MROWS) return;
    const float* p = in + (size_t)row * D_;
    float v[24];
    float s = 0.f;
    #pragma unroll
    for (int i = 0; i < 24; i++) { v[i] = p[lane + i*32]; s += v[i]; }
    #pragma unroll
    for (int o = 16; o > 0; o >>= 1) s += __shfl_xor_sync(0xffffffffu, s, o);
    float mean = s * (1.0f / D_);
    float vs = 0.f;
    #pragma unroll
    for (int i = 0; i < 24; i++) { float dx = v[i] - mean; vs += dx*dx; }
    #pragma unroll
    for (int o = 16; o > 0; o >>= 1) vs += __shfl_xor_sync(0xffffffffu, vs, o);
    float rs = rsqrtf(vs * (1.0f / D_) + 1e-5f);
    float* q = out + (size_t)row * D_;
    #pragma unroll
    for (int i = 0; i < 24; i++) {
        int c = lane + i*32;
        q[c] = (v[i] - mean) * rs * g[c] + bb[c];
    }
}

// ===== Softmax: warp per row of 577 =====
__global__ __launch_bounds__(256) void softmax_kernel(float* __restrict__ s) {
    int wid = threadIdx.x >> 5, lane = threadIdx.x & 31;
    int row = blockIdx.x * 8 + wid;
    float* p = s + (size_t)row * N_;
    float v[19];
    float mx = -1e30f;
    #pragma unroll
    for (int i = 0; i < 19; i++) {
        int c = lane + i*32;
        if (c < N_) { v[i] = p[c]; mx = fmaxf(mx, v[i]); }
    }
    #pragma unroll
    for (int o = 16; o > 0; o >>= 1) mx = fmaxf(mx, __shfl_xor_sync(0xffffffffu, mx, o));
    float sum = 0.f;
    #pragma unroll
    for (int i = 0; i < 19; i++) {
        int c = lane + i*32;
        if (c < N_) { float e = __expf(v[i] - mx); v[i] = e; sum += e; }
    }
    #pragma unroll
    for (int o = 16; o > 0; o >>= 1) sum += __shfl_xor_sync(0xffffffffu, sum, o);
    float inv = 1.0f / sum;
    #pragma unroll
    for (int i = 0; i < 19; i++) {
        int c = lane + i*32;
        if (c < N_) p[c] = v[i] * inv;
    }
}

// ===== Tensor-core TF32 GEMM =====
// MODE 0: dense  C[M,Nc] = epi(A[M,K] @ B[K,Nc] + bias)      (EPI 0:+b, 1:+b+res, 2:gelu(+b))
// MODE 1: scores S[z,i,j] = 0.125 * Q[z,i,:].K[z,j,:]        (K dim = HD)
// MODE 2: AV     O[z,i,d] = sum_j S[z,i,j] V[z,j,d]          (K dim = N_, guarded)
template<int BM, int BN, int WM, int WN, int MODE, int EPI>
__global__ __launch_bounds__((BM/WM)*(BN/WN)*32) void mma_gemm(
        const float* __restrict__ A, const float* __restrict__ Bm,
        const float* __restrict__ bias, const float* __restrict__ res,
        float* __restrict__ C, int M, int Nc, int K) {
    constexpr int BK = 16;
    constexpr int WARPS_N = BN / WN;
    constexpr int NT = (BM/WM) * (BN/WN) * 32;
    constexpr int MFRAG = WM / 16;
    constexpr int NFRAG = WN / 8;
    constexpr int LA4 = (MODE == 2) ? 0 : (BM*BK/4) / NT;
    constexpr int LAS = (MODE == 2) ? (BM*BK) / NT : 0;
    constexpr int LB4 = (BK*BN/4) / NT;

    __shared__ unsigned As[BM][BK + 4];     // [m][k], pad 4 -> conflict-free frag loads
    __shared__ unsigned Bs[BK][BN + 8];     // [k][n], pad 8 -> conflict-free frag loads

    int tid = threadIdx.x;
    int wid = tid >> 5, lane = tid & 31;
    int gid = lane >> 2, tg = lane & 3;
    int m_w = (wid / WARPS_N) * WM;
    int n_w = (wid % WARPS_N) * WN;
    int row0 = blockIdx.y * BM, col0 = blockIdx.x * BN;
    int z = blockIdx.z;
    int zb = z / NH_, zh = z % NH_;

    const float* Ab; const float* Bb;
    int lda;
    if constexpr (MODE == 0)      { Ab = A; Bb = Bm; lda = K; }
    else if constexpr (MODE == 1) { Ab = A + (size_t)(zb*N_)*D_ + zh*HD_;
                                    Bb = Bm + (size_t)(zb*N_)*D_ + zh*HD_; lda = D_; }
    else                          { Ab = A + (size_t)z*N_*N_; lda = N_;
                                    Bb = Bm + (size_t)(zb*N_)*D_ + zh*HD_; }

    float acc[MFRAG][NFRAG][4] = {};
    float4 ra[(LA4 > 0) ? LA4 : 1];
    float  ras[(LAS > 0) ? LAS : 1];
    float4 rb[LB4];

    auto load_g = [&](int kt) {
        if constexpr (MODE != 2) {
            #pragma unroll
            for (int p = 0; p < LA4; p++) {
                int idx = tid + p*NT;
                int r = idx >> 2, k4 = idx & 3;
                int gr = row0 + r;
                bool ok = (MODE == 0) ? (gr < M) : (gr < N_);
                ra[p] = ok ? *reinterpret_cast<const float4*>(Ab + (size_t)gr*lda + kt + k4*4)
                           : make_float4(0.f, 0.f, 0.f, 0.f);
            }
        } else {
            #pragma unroll
            for (int p = 0; p < LAS; p++) {
                int idx = tid + p*NT;
                int r = idx >> 4, kk = idx & 15;
                int gr = row0 + r;
                ras[p] = (gr < N_ && kt + kk < K) ? Ab[(size_t)gr*lda + kt + kk] : 0.f;
            }
        }
        if constexpr (MODE == 0) {
            #pragma unroll
            for (int p = 0; p < LB4; p++) {
                int idx = tid + p*NT;
                int kk = idx / (BN/4), n4 = idx % (BN/4);
                rb[p] = *reinterpret_cast<const float4*>(Bb + (size_t)(kt+kk)*Nc + col0 + n4*4);
            }
        } else if constexpr (MODE == 1) {
            #pragma unroll
            for (int p = 0; p < LB4; p++) {
                int idx = tid + p*NT;
                int n = idx >> 2, k4 = idx & 3;
                int gc = col0 + n;
                rb[p] = (gc < N_) ? *reinterpret_cast<const float4*>(Bb + (size_t)gc*D_ + kt + k4*4)
                                  : make_float4(0.f, 0.f, 0.f, 0.f);
            }
        } else {
            #pragma unroll
            for (int p = 0; p < LB4; p++) {
                int idx = tid + p*NT;
                int kk = idx / (BN/4), n4 = idx % (BN/4);
                rb[p] = (kt + kk < K) ? *reinterpret_cast<const float4*>(Bb + (size_t)(kt+kk)*D_ + n4*4)
                                      : make_float4(0.f, 0.f, 0.f, 0.f);
            }
        }
    };

    auto store_s = [&]() {
        if constexpr (MODE != 2) {
            #pragma unroll
            for (int p = 0; p < LA4; p++) {
                int idx = tid + p*NT;
                int r = idx >> 2, k4 = idx & 3;
                As[r][k4*4+0] = f2tf(ra[p].x);
                As[r][k4*4+1] = f2tf(ra[p].y);
                As[r][k4*4+2] = f2tf(ra[p].z);
                As[r][k4*4+3] = f2tf(ra[p].w);
            }
        } else {
            #pragma unroll
            for (int p = 0; p < LAS; p++) {
                int idx = tid + p*NT;
                int r = idx >> 4, kk = idx & 15;
                As[r][kk] = f2tf(ras[p]);
            }
        }
        if constexpr (MODE == 1) {
            #pragma unroll
            for (int p = 0; p < LB4; p++) {
                int idx = tid + p*NT;
                int n = idx >> 2, k4 = idx & 3;
                Bs[k4*4+0][n] = f2tf(rb[p].x);
                Bs[k4*4+1][n] = f2tf(rb[p].y);
                Bs[k4*4+2][n] = f2tf(rb[p].z);
                Bs[k4*4+3][n] = f2tf(rb[p].w);
            }
        } else {
            #pragma unroll
            for (int p = 0; p < LB4; p++) {
                int idx = tid + p*NT;
                int kk = idx / (BN/4), n4 = idx % (BN/4);
                uint4 u = make_uint4(f2tf(rb[p].x), f2tf(rb[p].y), f2tf(rb[p].z), f2tf(rb[p].w));
                *reinterpret_cast<uint4*>(&Bs[kk][n4*4]) = u;
            }
        }
    };

    int KT = (K + BK - 1) / BK;
    load_g(0);
    store_s();
    for (int t = 0; t < KT; t++) {
        __syncthreads();
        if (t + 1 < KT) load_g((t+1)*BK);
        #pragma unroll
        for (int ks = 0; ks < BK; ks += 8) {
            unsigned af[MFRAG][4], bf[NFRAG][2];
            #pragma unroll
            for (int mf = 0; mf < MFRAG; mf++) {
                int m = m_w + mf*16;
                af[mf][0] = As[m + gid    ][ks + tg    ];
                af[mf][1] = As[m + gid + 8][ks + tg    ];
                af[mf][2] = As[m + gid    ][ks + tg + 4];
                af[mf][3] = As[m + gid + 8][ks + tg + 4];
            }
            #pragma unroll
            for (int nf = 0; nf < NFRAG; nf++) {
                int n = n_w + nf*8;
                bf[nf][0] = Bs[ks + tg    ][n + gid];
                bf[nf][1] = Bs[ks + tg + 4][n + gid];
            }
            #pragma unroll
            for (int mf = 0; mf < MFRAG; mf++)
                #pragma unroll
                for (int nf = 0; nf < NFRAG; nf++) {
                    asm volatile(
                        "mma.sync.aligned.m16n8k8.row.col.f32.tf32.tf32.f32 "
                        "{%0,%1,%2,%3}, {%4,%5,%6,%7}, {%8,%9}, {%0,%1,%2,%3};\n"
                        : "+f"(acc[mf][nf][0]), "+f"(acc[mf][nf][1]),
                          "+f"(acc[mf][nf][2]), "+f"(acc[mf][nf][3])
                        : "r"(af[mf][0]), "r"(af[mf][1]), "r"(af[mf][2]), "r"(af[mf][3]),
                          "r"(bf[nf][0]), "r"(bf[nf][1]));
                }
        }
        __syncthreads();
        if (t + 1 < KT) store_s();
    }

    #pragma unroll
    for (int mf = 0; mf < MFRAG; mf++)
        #pragma unroll
        for (int nf = 0; nf < NFRAG; nf++) {
            int rbase = row0 + m_w + mf*16 + gid;
            int cbase = col0 + n_w + nf*8 + tg*2;
            #pragma unroll
            for (int e = 0; e < 4; e++) {
                int r = rbase + (e >> 1) * 8;
                int c = cbase + (e & 1);
                float v = acc[mf][nf][e];
                if constexpr (MODE == 0) {
                    if (r < M) {
                        v += bias[c];
                        if (EPI == 1) v += res[(size_t)r*Nc + c];
                        if (EPI == 2) v = 0.5f * v * (1.0f + erff(v * 0.7071067811865475f));
                        C[(size_t)r*Nc + c] = v;
                    }
                } else if constexpr (MODE == 1) {
                    if (r < N_ && c < N_) C[((size_t)z*N_ + r)*N_ + c] = v * 0.125f;
                } else {
                    if (r < N_) C[((size_t)(zb*N_ + r))*D_ + zh*HD_ + c] = v;
                }
            }
        }
}

// ===== Head =====
__global__ void head_kernel(const float* __restrict__ y, const float* __restrict__ hw,
                            const float* __restrict__ hb, float* __restrict__ out) {
    __shared__ float rowv[D_];
    int b = blockIdx.x;
    int tid = threadIdx.x;
    for (int c = tid; c < D_; c += 256) rowv[c] = y[((size_t)(b*N_))*D_ + c];
    __syncthreads();
    for (int c = tid; c < NCLS_; c += 256) {
        float s = hb[c];
        for (int d = 0; d < D_; d++) s = fmaf(rowv[d], hw[(size_t)d*NCLS_ + c], s);
        out[b*NCLS_ + c] = s;
    }
}

extern "C" void kernel_launch(void* const* d_in, const int* in_sizes, int n_in,
                              void* d_out, int out_size) {
    (void)in_sizes; (void)n_in; (void)out_size;
    const float* x       = (const float*)d_in[0];
    const float* proj_w  = (const float*)d_in[1];
    const float* proj_b  = (const float*)d_in[2];
    const float* cls_emb = (const float*)d_in[3];
    const float* pos_emb = (const float*)d_in[4];
    const float* ln1_g   = (const float*)d_in[5];
    const float* ln1_b   = (const float*)d_in[6];
    const float* qw = (const float*)d_in[7];
    const float* qb = (const float*)d_in[8];
    const float* kw = (const float*)d_in[9];
    const float* kb = (const float*)d_in[10];
    const float* vw = (const float*)d_in[11];
    const float* vb = (const float*)d_in[12];
    const float* ow = (const float*)d_in[13];
    const float* ob = (const float*)d_in[14];
    const float* ln2_g = (const float*)d_in[15];
    const float* ln2_b = (const float*)d_in[16];
    const float* fcw = (const float*)d_in[17];
    const float* fcb = (const float*)d_in[18];
    const float* pw  = (const float*)d_in[19];
    const float* pb  = (const float*)d_in[20];
    const float* lnf_g = (const float*)d_in[21];
    const float* lnf_b = (const float*)d_in[22];
    const float* head_w = (const float*)d_in[23];
    const float* head_b = (const float*)d_in[24];
    float* out = (float*)d_out;

    float *t_p, *h_p, *y_p, *q_p, *k_p, *v_p, *o_p, *m_p, *s_p;
    cudaGetSymbolAddress((void**)&t_p, g_t);
    cudaGetSymbolAddress((void**)&h_p, g_h);
    cudaGetSymbolAddress((void**)&y_p, g_y);
    cudaGetSymbolAddress((void**)&q_p, g_q);
    cudaGetSymbolAddress((void**)&k_p, g_k);
    cudaGetSymbolAddress((void**)&v_p, g_v);
    cudaGetSymbolAddress((void**)&o_p, g_o);
    cudaGetSymbolAddress((void**)&m_p, g_m);
    cudaGetSymbolAddress((void**)&s_p, g_s);

    // Patch embed
    patchify_kernel<<<(B_*NP_*D_ + 255)/256, 256>>>(x);
    mma_gemm<128,64,32,32,0,0><<<dim3(D_/64, PROWS/128), 256>>>(
        t_p, proj_w, proj_b, nullptr, y_p, PROWS, D_, D_);
    assemble_kernel<<<(MROWS*D_ + 255)/256, 256>>>(cls_emb, pos_emb);

    const int gMr = (MROWS + 127) / 128;       // 37
    const dim3 gD(D_/64, gMr);                 // 12 x 37
    const dim3 gF1(MLP_/128, gMr);             // 24 x 37
    const int nT128 = (N_ + 127) / 128;        // 5
    const dim3 gS(nT128, nT128, B_*NH_);       // 5 x 5 x 96
    const dim3 gAV(1, nT128, B_*NH_);          // 1 x 5 x 96
    const int lnB = (MROWS + 7) / 8;           // 577
    const int smB = (B_*NH_*N_) / 8;           // 6924

    for (int l = 0; l < L_; l++) {
        const float* qw_l = qw + (size_t)l*D_*D_;
        const float* kw_l = kw + (size_t)l*D_*D_;
        const float* vw_l = vw + (size_t)l*D_*D_;
        const float* ow_l = ow + (size_t)l*D_*D_;
        const float* fcw_l = fcw + (size_t)l*D_*MLP_;
        const float* pw_l  = pw  + (size_t)l*MLP_*D_;

        ln_kernel<<<lnB, 256>>>(h_p, y_p, ln1_g + l*D_, ln1_b + l*D_);
        mma_gemm<128,64,32,32,0,0><<<gD, 256>>>(y_p, qw_l, qb + l*D_, nullptr, q_p, MROWS, D_, D_);
        mma_gemm<128,64,32,32,0,0><<<gD, 256>>>(y_p, kw_l, kb + l*D_, nullptr, k_p, MROWS, D_, D_);
        mma_gemm<128,64,32,32,0,0><<<gD, 256>>>(y_p, vw_l, vb + l*D_, nullptr, v_p, MROWS, D_, D_);

        mma_gemm<128,128,64,32,1,0><<<gS, 256>>>(q_p, k_p, nullptr, nullptr, s_p, N_, N_, HD_);
        softmax_kernel<<<smB, 256>>>(s_p);
        mma_gemm<128,64,32,32,2,0><<<gAV, 256>>>(s_p, v_p, nullptr, nullptr, o_p, N_, HD_, N_);

        mma_gemm<128,64,32,32,0,1><<<gD, 256>>>(o_p, ow_l, ob + l*D_, h_p, h_p, MROWS, D_, D_);

        ln_kernel<<<lnB, 256>>>(h_p, y_p, ln2_g + l*D_, ln2_b + l*D_);
        mma_gemm<128,128,64,32,0,2><<<gF1, 256>>>(y_p, fcw_l, fcb + l*MLP_, nullptr, m_p, MROWS, MLP_, D_);
        mma_gemm<128,64,32,32,0,1><<<gD, 256>>>(m_p, pw_l, pb + l*D_, h_p, h_p, MROWS, D_, MLP_);
    }

    ln_kernel<<<lnB, 256>>>(h_p, y_p, lnf_g, lnf_b);
    head_kernel<<<B_, 256>>>(y_p, head_w, head_b, out);
}

// round 5
// speedup vs baseline: 3.9884x; 1.2038x over previous
#include <cuda_runtime.h>
#include <math.h>
#include <stdint.h>

// ===== Model config =====
#define B_   8
#define C_   3
#define H_   384
#define W_   384
#define P_   16
#define GH_  24
#define GW_  24
#define NP_  576
#define N_   577
#define D_   768
#define NH_  12
#define HD_  64
#define MLP_ 3072
#define L_   12
#define NCLS_ 1000
#define QD_  (3*D_)          // 2304 fused qkv width

#define MROWS (B_*N_)        // 4616
#define PROWS (B_*NP_)       // 4608

// ===== Scratch =====
__device__ float g_t[B_*NP_*D_];
__device__ float g_h[MROWS*D_];
__device__ float g_y[MROWS*D_];
__device__ float g_qkv[(size_t)MROWS*QD_];
__device__ float g_o[MROWS*D_];
__device__ float g_m[(size_t)MROWS*MLP_];
__device__ float g_s[(size_t)B_*NH_*N_*N_];
// tf32-rounded weight copies (natural [K,N] layout for mma B operand)
__device__ float g_qkvw[(size_t)L_*D_*QD_];
__device__ float g_qkvb[L_*QD_];
__device__ float g_oww[(size_t)L_*D_*D_];
__device__ float g_fcww[(size_t)L_*D_*MLP_];
__device__ float g_pww[(size_t)L_*MLP_*D_];
__device__ float g_projww[D_*D_];

__device__ __forceinline__ unsigned f2tf(float f) {
    unsigned u;
    asm("cvt.rna.tf32.f32 %0, %1;" : "=r"(u) : "f"(f));
    return u;
}
__device__ __forceinline__ float rtf(float f) { return __uint_as_float(f2tf(f)); }

__device__ __forceinline__ uint32_t smem_u32(const void* p) {
    uint32_t a;
    asm("{ .reg .u64 t; cvta.to.shared.u64 t, %1; cvt.u32.u64 %0, t; }" : "=r"(a) : "l"(p));
    return a;
}

// ===== Prep: tf32-round weight copies =====
__global__ void round_copy(const float* __restrict__ in, float* __restrict__ out, int n) {
    int i = blockIdx.x * 256 + threadIdx.x;
    if (i < n) out[i] = rtf(in[i]);
}
// fused qkv weight concat: dst[l][k][j], j<768:qw  768..1535:kw  else vw
__global__ void qkv_concat_w(const float* __restrict__ qw, const float* __restrict__ kw,
                             const float* __restrict__ vw, float* __restrict__ dst) {
    int i = blockIdx.x * 256 + threadIdx.x;
    if (i >= L_*D_*QD_) return;
    int j = i % QD_;
    int lk = i / QD_;            // l*768 + k
    int sel = j / D_, jj = j % D_;
    const float* src = (sel == 0) ? qw : (sel == 1) ? kw : vw;
    dst[i] = rtf(src[(size_t)lk * D_ + jj]);
}
__global__ void qkv_concat_b(const float* __restrict__ qb, const float* __restrict__ kb,
                             const float* __restrict__ vb, float* __restrict__ dst) {
    int i = blockIdx.x * 256 + threadIdx.x;
    if (i >= L_*QD_) return;
    int j = i % QD_, l = i / QD_;
    int sel = j / D_, jj = j % D_;
    const float* src = (sel == 0) ? qb : (sel == 1) ? kb : vb;
    dst[i] = src[l*D_ + jj];
}

// ===== Patchify (exact reference order), tf32-rounded out (feeds GEMM A) =====
__global__ void patchify_kernel(const float* __restrict__ x) {
    int idx = blockIdx.x * blockDim.x + threadIdx.x;
    if (idx >= B_*NP_*D_) return;
    const int BLK = B_*C_*GH_*GW_*P_;
    int p1 = idx / BLK;
    int r  = idx % BLK;
    int m  = r >> 4;
    int p2 = r & 15;
    int gw = m % GW_;  int m2 = m / GW_;
    int gh = m2 % GH_; int m3 = m2 / GH_;
    int c  = m3 % C_;  int bx = m3 / C_;
    g_t[idx] = rtf(x[(((size_t)(bx*C_ + c)*H_) + gh*P_ + p1)*W_ + gw*P_ + p2]);
}

__global__ void assemble_kernel(const float* __restrict__ cls, const float* __restrict__ pos) {
    int idx = blockIdx.x * blockDim.x + threadIdx.x;
    if (idx >= MROWS*D_) return;
    int d  = idx % D_;
    int rn = idx / D_;
    int n  = rn % N_;
    int b  = rn / N_;
    float v = (n == 0) ? cls[d] : g_y[((size_t)(b*NP_ + n - 1))*D_ + d];
    g_h[idx] = v + pos[n*D_ + d];
}

// ===== LayerNorm: warp per row, tf32-rounded output (feeds GEMM A) =====
__global__ __launch_bounds__(256) void ln_kernel(const float* __restrict__ in, float* __restrict__ out,
                          const float* __restrict__ g, const float* __restrict__ bb) {
    int wid = threadIdx.x >> 5, lane = threadIdx.x & 31;
    int row = blockIdx.x * 8 + wid;
    if (row >= MROWS) return;
    const float* p = in + (size_t)row * D_;
    float v[24];
    float s = 0.f;
    #pragma unroll
    for (int i = 0; i < 24; i++) { v[i] = p[lane + i*32]; s += v[i]; }
    #pragma unroll
    for (int o = 16; o > 0; o >>= 1) s += __shfl_xor_sync(0xffffffffu, s, o);
    float mean = s * (1.0f / D_);
    float vs = 0.f;
    #pragma unroll
    for (int i = 0; i < 24; i++) { float dx = v[i] - mean; vs += dx*dx; }
    #pragma unroll
    for (int o = 16; o > 0; o >>= 1) vs += __shfl_xor_sync(0xffffffffu, vs, o);
    float rs = rsqrtf(vs * (1.0f / D_) + 1e-5f);
    float* q = out + (size_t)row * D_;
    #pragma unroll
    for (int i = 0; i < 24; i++) {
        int c = lane + i*32;
        q[c] = rtf((v[i] - mean) * rs * g[c] + bb[c]);
    }
}

// ===== Softmax: warp per row of 577, tf32-rounded output (feeds AV A) =====
__global__ __launch_bounds__(256) void softmax_kernel(float* __restrict__ s) {
    int wid = threadIdx.x >> 5, lane = threadIdx.x & 31;
    int row = blockIdx.x * 8 + wid;
    float* p = s + (size_t)row * N_;
    float v[19];
    float mx = -1e30f;
    #pragma unroll
    for (int i = 0; i < 19; i++) {
        int c = lane + i*32;
        if (c < N_) { v[i] = p[c]; mx = fmaxf(mx, v[i]); }
    }
    #pragma unroll
    for (int o = 16; o > 0; o >>= 1) mx = fmaxf(mx, __shfl_xor_sync(0xffffffffu, mx, o));
    float sum = 0.f;
    #pragma unroll
    for (int i = 0; i < 19; i++) {
        int c = lane + i*32;
        if (c < N_) { float e = __expf(v[i] - mx); v[i] = e; sum += e; }
    }
    #pragma unroll
    for (int o = 16; o > 0; o >>= 1) sum += __shfl_xor_sync(0xffffffffu, sum, o);
    float inv = 1.0f / sum;
    #pragma unroll
    for (int i = 0; i < 19; i++) {
        int c = lane + i*32;
        if (c < N_) p[c] = rtf(v[i] * inv);
    }
}

// ===== Dense TF32 GEMM (cp.async double-buffered, BM=128 BN=128 BK=32) =====
// C = epi(A[M,K] @ B[K,Nc] + bias);  inputs already tf32-rounded bits.
// EPI 0:+b  1:+b+res  2:gelu(+b).  ROUND: tf32-round the output.
// Requirements: K%32==0, Nc%128==0.
#define GA_SMEM (2*(128*144) + 2*(32*544))    // 71680 bytes
template<int EPI, int ROUND>
__global__ __launch_bounds__(256) void tf32_gemm(
        const float* __restrict__ A, const float* __restrict__ Bw,
        const float* __restrict__ bias, const float* __restrict__ res,
        float* __restrict__ C, int M, int Nc, int K) {
    extern __shared__ char smem[];
    const uint32_t AS0 = 0, AS1 = 128*144, BS0 = 2*128*144, BS1 = 2*128*144 + 32*544;
    uint32_t sbase = smem_u32(smem);

    int tid = threadIdx.x;
    int wid = tid >> 5, lane = tid & 31;
    int gid = lane >> 2, tg = lane & 3;
    int m_w = (wid >> 2) * 64;          // 2 warp-rows
    int n_w = (wid & 3) * 32;           // 4 warp-cols
    int row0 = blockIdx.y * 128, col0 = blockIdx.x * 128;

    float acc[4][4][4] = {};

    auto load_stage = [&](int t, int bb) {
        uint32_t abase = sbase + (bb ? AS1 : AS0);
        uint32_t bbase = sbase + (bb ? BS1 : BS0);
        int kt = t << 5;
        #pragma unroll
        for (int p = 0; p < 4; p++) {
            int idx = tid + p*256;
            int r = idx >> 3, c = idx & 7;
            int gr = row0 + r;
            const float* src = A + (size_t)(gr < M ? gr : M-1)*K + kt + c*4;
            unsigned sz = (gr < M) ? 16u : 0u;
            asm volatile("cp.async.ca.shared.global [%0], [%1], 16, %2;" ::
                "r"(abase + r*144 + c*16), "l"(src), "r"(sz));
        }
        #pragma unroll
        for (int p = 0; p < 4; p++) {
            int idx = tid + p*256;
            int r = idx >> 5, c = idx & 31;
            const float* src = Bw + (size_t)(kt + r)*Nc + col0 + c*4;
            asm volatile("cp.async.ca.shared.global [%0], [%1], 16;" ::
                "r"(bbase + r*544 + c*16), "l"(src));
        }
        asm volatile("cp.async.commit_group;");
    };

    int KT = K >> 5;
    load_stage(0, 0);
    for (int t = 0; t < KT; t++) {
        int bb = t & 1;
        if (t + 1 < KT) {
            load_stage(t+1, bb^1);
            asm volatile("cp.async.wait_group 1;");
        } else {
            asm volatile("cp.async.wait_group 0;");
        }
        __syncthreads();
        const float* as = reinterpret_cast<const float*>(smem + (bb ? AS1 : AS0));
        const float* bs = reinterpret_cast<const float*>(smem + (bb ? BS1 : BS0));
        #pragma unroll
        for (int ks = 0; ks < 32; ks += 8) {
            unsigned af[4][4], bf[4][2];
            #pragma unroll
            for (int mf = 0; mf < 4; mf++) {
                int m = m_w + mf*16;
                af[mf][0] = __float_as_uint(as[(m+gid  )*36 + ks+tg  ]);
                af[mf][1] = __float_as_uint(as[(m+gid+8)*36 + ks+tg  ]);
                af[mf][2] = __float_as_uint(as[(m+gid  )*36 + ks+tg+4]);
                af[mf][3] = __float_as_uint(as[(m+gid+8)*36 + ks+tg+4]);
            }
            #pragma unroll
            for (int nf = 0; nf < 4; nf++) {
                int n = n_w + nf*8;
                bf[nf][0] = __float_as_uint(bs[(ks+tg  )*136 + n+gid]);
                bf[nf][1] = __float_as_uint(bs[(ks+tg+4)*136 + n+gid]);
            }
            #pragma unroll
            for (int mf = 0; mf < 4; mf++)
                #pragma unroll
                for (int nf = 0; nf < 4; nf++) {
                    asm volatile(
                        "mma.sync.aligned.m16n8k8.row.col.f32.tf32.tf32.f32 "
                        "{%0,%1,%2,%3}, {%4,%5,%6,%7}, {%8,%9}, {%0,%1,%2,%3};\n"
                        : "+f"(acc[mf][nf][0]), "+f"(acc[mf][nf][1]),
                          "+f"(acc[mf][nf][2]), "+f"(acc[mf][nf][3])
                        : "r"(af[mf][0]), "r"(af[mf][1]), "r"(af[mf][2]), "r"(af[mf][3]),
                          "r"(bf[nf][0]), "r"(bf[nf][1]));
                }
        }
        __syncthreads();
    }

    #pragma unroll
    for (int mf = 0; mf < 4; mf++) {
        #pragma unroll
        for (int nf = 0; nf < 4; nf++) {
            int r0 = row0 + m_w + mf*16 + gid;
            int c0 = col0 + n_w + nf*8 + tg*2;
            float b0 = bias[c0], b1 = bias[c0+1];
            #pragma unroll
            for (int half = 0; half < 2; half++) {
                int r = r0 + half*8;
                if (r < M) {
                    float v0 = acc[mf][nf][half*2+0] + b0;
                    float v1 = acc[mf][nf][half*2+1] + b1;
                    if (EPI == 1) {
                        float2 rv = *reinterpret_cast<const float2*>(res + (size_t)r*Nc + c0);
                        v0 += rv.x; v1 += rv.y;
                    }
                    if (EPI == 2) {
                        v0 = 0.5f * v0 * (1.0f + erff(v0 * 0.7071067811865475f));
                        v1 = 0.5f * v1 * (1.0f + erff(v1 * 0.7071067811865475f));
                    }
                    if (ROUND) { v0 = rtf(v0); v1 = rtf(v1); }
                    *reinterpret_cast<float2*>(C + (size_t)r*Nc + c0) = make_float2(v0, v1);
                }
            }
        }
    }
}

// ===== mma.sync attention GEMMs over fused qkv buffer =====
// MODE 1: S[z,i,j] = 0.125*q_i.k_j (K=HD)    MODE 2: O = S@V (K=N_, rounded out)
template<int BM, int BN, int WM, int WN, int MODE>
__global__ __launch_bounds__((BM/WM)*(BN/WN)*32) void mma_gemm(
        const float* __restrict__ A, const float* __restrict__ Bm,
        float* __restrict__ C, int K) {
    constexpr int BK = 16;
    constexpr int WARPS_N = BN / WN;
    constexpr int NT = (BM/WM) * (BN/WN) * 32;
    constexpr int MFRAG = WM / 16;
    constexpr int NFRAG = WN / 8;
    constexpr int LA4 = (MODE == 2) ? 0 : (BM*BK/4) / NT;
    constexpr int LAS = (MODE == 2) ? (BM*BK) / NT : 0;
    constexpr int LB4 = (BK*BN/4) / NT;

    __shared__ unsigned As[BM][BK + 4];
    __shared__ unsigned Bs[BK][BN + 8];

    int tid = threadIdx.x;
    int wid = tid >> 5, lane = tid & 31;
    int gid = lane >> 2, tg = lane & 3;
    int m_w = (wid / WARPS_N) * WM;
    int n_w = (wid % WARPS_N) * WN;
    int row0 = blockIdx.y * BM, col0 = blockIdx.x * BN;
    int z = blockIdx.z;
    int zb = z / NH_, zh = z % NH_;

    const float* Ab; const float* Bb;
    int lda;
    if constexpr (MODE == 1) { Ab = A + (size_t)(zb*N_)*QD_ + zh*HD_; lda = QD_;
                               Bb = A + (size_t)(zb*N_)*QD_ + D_ + zh*HD_; }
    else                     { Ab = A + (size_t)z*N_*N_; lda = N_;
                               Bb = Bm + (size_t)(zb*N_)*QD_ + 2*D_ + zh*HD_; }

    float acc[MFRAG][NFRAG][4] = {};
    float4 ra[(LA4 > 0) ? LA4 : 1];
    float  ras[(LAS > 0) ? LAS : 1];
    float4 rb[LB4];

    auto load_g = [&](int kt) {
        if constexpr (MODE != 2) {
            #pragma unroll
            for (int p = 0; p < LA4; p++) {
                int idx = tid + p*NT;
                int r = idx >> 2, k4 = idx & 3;
                int gr = row0 + r;
                ra[p] = (gr < N_) ? *reinterpret_cast<const float4*>(Ab + (size_t)gr*lda + kt + k4*4)
                                  : make_float4(0.f, 0.f, 0.f, 0.f);
            }
        } else {
            #pragma unroll
            for (int p = 0; p < LAS; p++) {
                int idx = tid + p*NT;
                int r = idx >> 4, kk = idx & 15;
                int gr = row0 + r;
                ras[p] = (gr < N_ && kt + kk < K) ? Ab[(size_t)gr*lda + kt + kk] : 0.f;
            }
        }
        if constexpr (MODE == 1) {
            #pragma unroll
            for (int p = 0; p < LB4; p++) {
                int idx = tid + p*NT;
                int n = idx >> 2, k4 = idx & 3;
                int gc = col0 + n;
                rb[p] = (gc < N_) ? *reinterpret_cast<const float4*>(Bb + (size_t)gc*QD_ + kt + k4*4)
                                  : make_float4(0.f, 0.f, 0.f, 0.f);
            }
        } else {
            #pragma unroll
            for (int p = 0; p < LB4; p++) {
                int idx = tid + p*NT;
                int kk = idx / (BN/4), n4 = idx % (BN/4);
                rb[p] = (kt + kk < K) ? *reinterpret_cast<const float4*>(Bb + (size_t)(kt+kk)*QD_ + n4*4)
                                      : make_float4(0.f, 0.f, 0.f, 0.f);
            }
        }
    };

    auto store_s = [&]() {
        if constexpr (MODE != 2) {
            #pragma unroll
            for (int p = 0; p < LA4; p++) {
                int idx = tid + p*NT;
                int r = idx >> 2, k4 = idx & 3;
                As[r][k4*4+0] = __float_as_uint(ra[p].x);
                As[r][k4*4+1] = __float_as_uint(ra[p].y);
                As[r][k4*4+2] = __float_as_uint(ra[p].z);
                As[r][k4*4+3] = __float_as_uint(ra[p].w);
            }
        } else {
            #pragma unroll
            for (int p = 0; p < LAS; p++) {
                int idx = tid + p*NT;
                int r = idx >> 4, kk = idx & 15;
                As[r][kk] = __float_as_uint(ras[p]);
            }
        }
        if constexpr (MODE == 1) {
            #pragma unroll
            for (int p = 0; p < LB4; p++) {
                int idx = tid + p*NT;
                int n = idx >> 2, k4 = idx & 3;
                Bs[k4*4+0][n] = __float_as_uint(rb[p].x);
                Bs[k4*4+1][n] = __float_as_uint(rb[p].y);
                Bs[k4*4+2][n] = __float_as_uint(rb[p].z);
                Bs[k4*4+3][n] = __float_as_uint(rb[p].w);
            }
        } else {
            #pragma unroll
            for (int p = 0; p < LB4; p++) {
                int idx = tid + p*NT;
                int kk = idx / (BN/4), n4 = idx % (BN/4);
                uint4 u = make_uint4(__float_as_uint(rb[p].x), __float_as_uint(rb[p].y),
                                     __float_as_uint(rb[p].z), __float_as_uint(rb[p].w));
                *reinterpret_cast<uint4*>(&Bs[kk][n4*4]) = u;
            }
        }
    };

    int KT = (K + BK - 1) / BK;
    load_g(0);
    store_s();
    for (int t = 0; t < KT; t++) {
        __syncthreads();
        if (t + 1 < KT) load_g((t+1)*BK);
        #pragma unroll
        for (int ks = 0; ks < BK; ks += 8) {
            unsigned af[MFRAG][4], bf[NFRAG][2];
            #pragma unroll
            for (int mf = 0; mf < MFRAG; mf++) {
                int m = m_w + mf*16;
                af[mf][0] = As[m + gid    ][ks + tg    ];
                af[mf][1] = As[m + gid + 8][ks + tg    ];
                af[mf][2] = As[m + gid    ][ks + tg + 4];
                af[mf][3] = As[m + gid + 8][ks + tg + 4];
            }
            #pragma unroll
            for (int nf = 0; nf < NFRAG; nf++) {
                int n = n_w + nf*8;
                bf[nf][0] = Bs[ks + tg    ][n + gid];
                bf[nf][1] = Bs[ks + tg + 4][n + gid];
            }
            #pragma unroll
            for (int mf = 0; mf < MFRAG; mf++)
                #pragma unroll
                for (int nf = 0; nf < NFRAG; nf++) {
                    asm volatile(
                        "mma.sync.aligned.m16n8k8.row.col.f32.tf32.tf32.f32 "
                        "{%0,%1,%2,%3}, {%4,%5,%6,%7}, {%8,%9}, {%0,%1,%2,%3};\n"
                        : "+f"(acc[mf][nf][0]), "+f"(acc[mf][nf][1]),
                          "+f"(acc[mf][nf][2]), "+f"(acc[mf][nf][3])
                        : "r"(af[mf][0]), "r"(af[mf][1]), "r"(af[mf][2]), "r"(af[mf][3]),
                          "r"(bf[nf][0]), "r"(bf[nf][1]));
                }
        }
        __syncthreads();
        if (t + 1 < KT) store_s();
    }

    #pragma unroll
    for (int mf = 0; mf < MFRAG; mf++)
        #pragma unroll
        for (int nf = 0; nf < NFRAG; nf++) {
            int rbase = row0 + m_w + mf*16 + gid;
            int cbase = col0 + n_w + nf*8 + tg*2;
            #pragma unroll
            for (int e = 0; e < 4; e++) {
                int r = rbase + (e >> 1) * 8;
                int c = cbase + (e & 1);
                float v = acc[mf][nf][e];
                if constexpr (MODE == 1) {
                    if (r < N_ && c < N_) C[((size_t)z*N_ + r)*N_ + c] = v * 0.125f;
                } else {
                    if (r < N_) C[((size_t)(zb*N_ + r))*D_ + zh*HD_ + c] = rtf(v);
                }
            }
        }
}

// ===== Head =====
__global__ void head_kernel(const float* __restrict__ y, const float* __restrict__ hw,
                            const float* __restrict__ hb, float* __restrict__ out) {
    __shared__ float rowv[D_];
    int b = blockIdx.x;
    int tid = threadIdx.x;
    for (int c = tid; c < D_; c += 256) rowv[c] = y[((size_t)(b*N_))*D_ + c];
    __syncthreads();
    for (int c = tid; c < NCLS_; c += 256) {
        float s = hb[c];
        for (int d = 0; d < D_; d++) s = fmaf(rowv[d], hw[(size_t)d*NCLS_ + c], s);
        out[b*NCLS_ + c] = s;
    }
}

extern "C" void kernel_launch(void* const* d_in, const int* in_sizes, int n_in,
                              void* d_out, int out_size) {
    (void)in_sizes; (void)n_in; (void)out_size;
    const float* x       = (const float*)d_in[0];
    const float* proj_w  = (const float*)d_in[1];
    const float* proj_b  = (const float*)d_in[2];
    const float* cls_emb = (const float*)d_in[3];
    const float* pos_emb = (const float*)d_in[4];
    const float* ln1_g   = (const float*)d_in[5];
    const float* ln1_b   = (const float*)d_in[6];
    const float* qw = (const float*)d_in[7];
    const float* qb = (const float*)d_in[8];
    const float* kw = (const float*)d_in[9];
    const float* kb = (const float*)d_in[10];
    const float* vw = (const float*)d_in[11];
    const float* vb = (const float*)d_in[12];
    const float* ow = (const float*)d_in[13];
    const float* ob = (const float*)d_in[14];
    const float* ln2_g = (const float*)d_in[15];
    const float* ln2_b = (const float*)d_in[16];
    const float* fcw = (const float*)d_in[17];
    const float* fcb = (const float*)d_in[18];
    const float* pw  = (const float*)d_in[19];
    const float* pb  = (const float*)d_in[20];
    const float* lnf_g = (const float*)d_in[21];
    const float* lnf_b = (const float*)d_in[22];
    const float* head_w = (const float*)d_in[23];
    const float* head_b = (const float*)d_in[24];
    float* out = (float*)d_out;

    float *t_p, *h_p, *y_p, *qkv_p, *o_p, *m_p, *s_p;
    float *qkvw, *qkvb, *oww, *fcww, *pww, *projww;
    cudaGetSymbolAddress((void**)&t_p, g_t);
    cudaGetSymbolAddress((void**)&h_p, g_h);
    cudaGetSymbolAddress((void**)&y_p, g_y);
    cudaGetSymbolAddress((void**)&qkv_p, g_qkv);
    cudaGetSymbolAddress((void**)&o_p, g_o);
    cudaGetSymbolAddress((void**)&m_p, g_m);
    cudaGetSymbolAddress((void**)&s_p, g_s);
    cudaGetSymbolAddress((void**)&qkvw, g_qkvw);
    cudaGetSymbolAddress((void**)&qkvb, g_qkvb);
    cudaGetSymbolAddress((void**)&oww, g_oww);
    cudaGetSymbolAddress((void**)&fcww, g_fcww);
    cudaGetSymbolAddress((void**)&pww, g_pww);
    cudaGetSymbolAddress((void**)&projww, g_projww);

    cudaFuncSetAttribute(tf32_gemm<0,0>, cudaFuncAttributeMaxDynamicSharedMemorySize, GA_SMEM);
    cudaFuncSetAttribute(tf32_gemm<0,1>, cudaFuncAttributeMaxDynamicSharedMemorySize, GA_SMEM);
    cudaFuncSetAttribute(tf32_gemm<1,0>, cudaFuncAttributeMaxDynamicSharedMemorySize, GA_SMEM);
    cudaFuncSetAttribute(tf32_gemm<2,1>, cudaFuncAttributeMaxDynamicSharedMemorySize, GA_SMEM);

    // ---- Weight prep (tf32 round copies, qkv fusion) ----
    qkv_concat_w<<<(L_*D_*QD_ + 255)/256, 256>>>(qw, kw, vw, qkvw);
    qkv_concat_b<<<(L_*QD_ + 255)/256, 256>>>(qb, kb, vb, qkvb);
    round_copy<<<(L_*D_*D_ + 255)/256, 256>>>(ow, oww, L_*D_*D_);
    round_copy<<<(L_*D_*MLP_ + 255)/256, 256>>>(fcw, fcww, L_*D_*MLP_);
    round_copy<<<(L_*MLP_*D_ + 255)/256, 256>>>(pw, pww, L_*MLP_*D_);
    round_copy<<<(D_*D_ + 255)/256, 256>>>(proj_w, projww, D_*D_);

    // ---- Patch embed ----
    patchify_kernel<<<(B_*NP_*D_ + 255)/256, 256>>>(x);
    tf32_gemm<0,0><<<dim3(D_/128, PROWS/128), 256, GA_SMEM>>>(
        t_p, projww, proj_b, nullptr, y_p, PROWS, D_, D_);
    assemble_kernel<<<(MROWS*D_ + 255)/256, 256>>>(cls_emb, pos_emb);

    const int gMr = (MROWS + 127) / 128;           // 37
    const dim3 gQKV(QD_/128, gMr);                 // 18 x 37
    const dim3 gD(D_/128, gMr);                    // 6 x 37
    const dim3 gF1(MLP_/128, gMr);                 // 24 x 37
    const int nT128 = (N_ + 127) / 128;            // 5
    const dim3 gS(nT128, nT128, B_*NH_);
    const dim3 gAV(1, nT128, B_*NH_);
    const int lnB = (MROWS + 7) / 8;
    const int smB = (B_*NH_*N_) / 8;

    for (int l = 0; l < L_; l++) {
        float* qkvw_l = qkvw + (size_t)l*D_*QD_;
        float* oww_l  = oww  + (size_t)l*D_*D_;
        float* fcww_l = fcww + (size_t)l*D_*MLP_;
        float* pww_l  = pww  + (size_t)l*MLP_*D_;

        ln_kernel<<<lnB, 256>>>(h_p, y_p, ln1_g + l*D_, ln1_b + l*D_);
        tf32_gemm<0,1><<<gQKV, 256, GA_SMEM>>>(y_p, qkvw_l, qkvb + l*QD_, nullptr,
                                               qkv_p, MROWS, QD_, D_);

        mma_gemm<128,128,64,32,1><<<gS, 256>>>(qkv_p, nullptr, s_p, HD_);
        softmax_kernel<<<smB, 256>>>(s_p);
        mma_gemm<128,64,32,32,2><<<gAV, 256>>>(s_p, qkv_p, o_p, N_);

        tf32_gemm<1,0><<<gD, 256, GA_SMEM>>>(o_p, oww_l, ob + l*D_, h_p, h_p, MROWS, D_, D_);

        ln_kernel<<<lnB, 256>>>(h_p, y_p, ln2_g + l*D_, ln2_b + l*D_);
        tf32_gemm<2,1><<<gF1, 256, GA_SMEM>>>(y_p, fcww_l, fcb + l*MLP_, nullptr,
                                              m_p, MROWS, MLP_, D_);
        tf32_gemm<1,0><<<gD, 256, GA_SMEM>>>(m_p, pww_l, pb + l*D_, h_p, h_p, MROWS, D_, MLP_);
    }

    ln_kernel<<<lnB, 256>>>(h_p, y_p, lnf_g, lnf_b);
    head_kernel<<<B_, 256>>>(y_p, head_w, head_b, out);
}

// round 6
// speedup vs baseline: 4.0061x; 1.0044x over previous
#include <cuda_runtime.h>
#include <math.h>
#include <stdint.h>

// ===== Model config =====
#define B_   8
#define C_   3
#define H_   384
#define W_   384
#define P_   16
#define GH_  24
#define GW_  24
#define NP_  576
#define N_   577
#define D_   768
#define NH_  12
#define HD_  64
#define MLP_ 3072
#define L_   12
#define NCLS_ 1000
#define QD_  (3*D_)          // 2304 fused qkv width

#define MROWS (B_*N_)        // 4616
#define PROWS (B_*NP_)       // 4608

// ===== Scratch =====
__device__ float g_t[B_*NP_*D_];
__device__ float g_h[MROWS*D_];
__device__ float g_y[MROWS*D_];
__device__ float g_qkv[(size_t)MROWS*QD_];
__device__ float g_o[MROWS*D_];
__device__ float g_m[(size_t)MROWS*MLP_];
__device__ float g_s[(size_t)B_*NH_*N_*N_];
// tf32-rounded weight copies (natural [K,N] layout for mma B operand)
__device__ float g_qkvw[(size_t)L_*D_*QD_];
__device__ float g_qkvb[L_*QD_];
__device__ float g_oww[(size_t)L_*D_*D_];
__device__ float g_fcww[(size_t)L_*D_*MLP_];
__device__ float g_pww[(size_t)L_*MLP_*D_];
__device__ float g_projww[D_*D_];

__device__ __forceinline__ unsigned f2tf(float f) {
    unsigned u;
    asm("cvt.rna.tf32.f32 %0, %1;" : "=r"(u) : "f"(f));
    return u;
}
__device__ __forceinline__ float rtf(float f) { return __uint_as_float(f2tf(f)); }

__device__ __forceinline__ uint32_t smem_u32(const void* p) {
    uint32_t a;
    asm("{ .reg .u64 t; cvta.to.shared.u64 t, %1; cvt.u32.u64 %0, t; }" : "=r"(a) : "l"(p));
    return a;
}

// ===== Prep: tf32-round weight copies =====
__global__ void round_copy(const float* __restrict__ in, float* __restrict__ out, int n) {
    int i = blockIdx.x * 256 + threadIdx.x;
    if (i < n) out[i] = rtf(in[i]);
}
// fused qkv weight concat: dst[l][k][j], j<768:qw  768..1535:kw  else vw
__global__ void qkv_concat_w(const float* __restrict__ qw, const float* __restrict__ kw,
                             const float* __restrict__ vw, float* __restrict__ dst) {
    int i = blockIdx.x * 256 + threadIdx.x;
    if (i >= L_*D_*QD_) return;
    int j = i % QD_;
    int lk = i / QD_;            // l*768 + k
    int sel = j / D_, jj = j % D_;
    const float* src = (sel == 0) ? qw : (sel == 1) ? kw : vw;
    dst[i] = rtf(src[(size_t)lk * D_ + jj]);
}
__global__ void qkv_concat_b(const float* __restrict__ qb, const float* __restrict__ kb,
                             const float* __restrict__ vb, float* __restrict__ dst) {
    int i = blockIdx.x * 256 + threadIdx.x;
    if (i >= L_*QD_) return;
    int j = i % QD_, l = i / QD_;
    int sel = j / D_, jj = j % D_;
    const float* src = (sel == 0) ? qb : (sel == 1) ? kb : vb;
    dst[i] = src[l*D_ + jj];
}

// ===== Patchify (exact reference order), tf32-rounded out (feeds GEMM A) =====
__global__ void patchify_kernel(const float* __restrict__ x) {
    int idx = blockIdx.x * blockDim.x + threadIdx.x;
    if (idx >= B_*NP_*D_) return;
    const int BLK = B_*C_*GH_*GW_*P_;
    int p1 = idx / BLK;
    int r  = idx % BLK;
    int m  = r >> 4;
    int p2 = r & 15;
    int gw = m % GW_;  int m2 = m / GW_;
    int gh = m2 % GH_; int m3 = m2 / GH_;
    int c  = m3 % C_;  int bx = m3 / C_;
    g_t[idx] = rtf(x[(((size_t)(bx*C_ + c)*H_) + gh*P_ + p1)*W_ + gw*P_ + p2]);
}

__global__ void assemble_kernel(const float* __restrict__ cls, const float* __restrict__ pos) {
    int idx = blockIdx.x * blockDim.x + threadIdx.x;
    if (idx >= MROWS*D_) return;
    int d  = idx % D_;
    int rn = idx / D_;
    int n  = rn % N_;
    int b  = rn / N_;
    float v = (n == 0) ? cls[d] : g_y[((size_t)(b*NP_ + n - 1))*D_ + d];
    g_h[idx] = v + pos[n*D_ + d];
}

// ===== LayerNorm: warp per row, tf32-rounded output (feeds GEMM A) =====
__global__ __launch_bounds__(256) void ln_kernel(const float* __restrict__ in, float* __restrict__ out,
                          const float* __restrict__ g, const float* __restrict__ bb) {
    int wid = threadIdx.x >> 5, lane = threadIdx.x & 31;
    int row = blockIdx.x * 8 + wid;
    if (row >= MROWS) return;
    const float* p = in + (size_t)row * D_;
    float v[24];
    float s = 0.f;
    #pragma unroll
    for (int i = 0; i < 24; i++) { v[i] = p[lane + i*32]; s += v[i]; }
    #pragma unroll
    for (int o = 16; o > 0; o >>= 1) s += __shfl_xor_sync(0xffffffffu, s, o);
    float mean = s * (1.0f / D_);
    float vs = 0.f;
    #pragma unroll
    for (int i = 0; i < 24; i++) { float dx = v[i] - mean; vs += dx*dx; }
    #pragma unroll
    for (int o = 16; o > 0; o >>= 1) vs += __shfl_xor_sync(0xffffffffu, vs, o);
    float rs = rsqrtf(vs * (1.0f / D_) + 1e-5f);
    float* q = out + (size_t)row * D_;
    #pragma unroll
    for (int i = 0; i < 24; i++) {
        int c = lane + i*32;
        q[c] = rtf((v[i] - mean) * rs * g[c] + bb[c]);
    }
}

// ===== Softmax: warp per row of 577, tf32-rounded output (feeds AV A) =====
__global__ __launch_bounds__(256) void softmax_kernel(float* __restrict__ s) {
    int wid = threadIdx.x >> 5, lane = threadIdx.x & 31;
    int row = blockIdx.x * 8 + wid;
    float* p = s + (size_t)row * N_;
    float v[19];
    float mx = -1e30f;
    #pragma unroll
    for (int i = 0; i < 19; i++) {
        int c = lane + i*32;
        if (c < N_) { v[i] = p[c]; mx = fmaxf(mx, v[i]); }
    }
    #pragma unroll
    for (int o = 16; o > 0; o >>= 1) mx = fmaxf(mx, __shfl_xor_sync(0xffffffffu, mx, o));
    float sum = 0.f;
    #pragma unroll
    for (int i = 0; i < 19; i++) {
        int c = lane + i*32;
        if (c < N_) { float e = __expf(v[i] - mx); v[i] = e; sum += e; }
    }
    #pragma unroll
    for (int o = 16; o > 0; o >>= 1) sum += __shfl_xor_sync(0xffffffffu, sum, o);
    float inv = 1.0f / sum;
    #pragma unroll
    for (int i = 0; i < 19; i++) {
        int c = lane + i*32;
        if (c < N_) p[c] = rtf(v[i] * inv);
    }
}

// ===== Dense TF32 GEMM (cp.async double-buffered, BM=128 BN=128 BK=32) =====
// C = epi(A[M,K] @ B[K,Nc] + bias);  inputs already tf32-rounded bits.
// EPI 0:+b  1:+b+res  2:gelu(+b).  ROUND: tf32-round the output.
// Requirements: K%32==0, Nc%128==0.
#define GA_SMEM (2*(128*144) + 2*(32*544))    // 71680 bytes
template<int EPI, int ROUND>
__global__ __launch_bounds__(256) void tf32_gemm(
        const float* __restrict__ A, const float* __restrict__ Bw,
        const float* __restrict__ bias, const float* __restrict__ res,
        float* __restrict__ C, int M, int Nc, int K) {
    extern __shared__ char smem[];
    const uint32_t AS0 = 0, AS1 = 128*144, BS0 = 2*128*144, BS1 = 2*128*144 + 32*544;
    uint32_t sbase = smem_u32(smem);

    int tid = threadIdx.x;
    int wid = tid >> 5, lane = tid & 31;
    int gid = lane >> 2, tg = lane & 3;
    int m_w = (wid >> 2) * 64;          // 2 warp-rows
    int n_w = (wid & 3) * 32;           // 4 warp-cols
    int row0 = blockIdx.y * 128, col0 = blockIdx.x * 128;

    float acc[4][4][4] = {};

    auto load_stage = [&](int t, int bb) {
        uint32_t abase = sbase + (bb ? AS1 : AS0);
        uint32_t bbase = sbase + (bb ? BS1 : BS0);
        int kt = t << 5;
        #pragma unroll
        for (int p = 0; p < 4; p++) {
            int idx = tid + p*256;
            int r = idx >> 3, c = idx & 7;
            int gr = row0 + r;
            const float* src = A + (size_t)(gr < M ? gr : M-1)*K + kt + c*4;
            unsigned sz = (gr < M) ? 16u : 0u;
            asm volatile("cp.async.ca.shared.global [%0], [%1], 16, %2;" ::
                "r"(abase + r*144 + c*16), "l"(src), "r"(sz));
        }
        #pragma unroll
        for (int p = 0; p < 4; p++) {
            int idx = tid + p*256;
            int r = idx >> 5, c = idx & 31;
            const float* src = Bw + (size_t)(kt + r)*Nc + col0 + c*4;
            asm volatile("cp.async.ca.shared.global [%0], [%1], 16;" ::
                "r"(bbase + r*544 + c*16), "l"(src));
        }
        asm volatile("cp.async.commit_group;");
    };

    int KT = K >> 5;
    load_stage(0, 0);
    for (int t = 0; t < KT; t++) {
        int bb = t & 1;
        if (t + 1 < KT) {
            load_stage(t+1, bb^1);
            asm volatile("cp.async.wait_group 1;");
        } else {
            asm volatile("cp.async.wait_group 0;");
        }
        __syncthreads();
        const float* as = reinterpret_cast<const float*>(smem + (bb ? AS1 : AS0));
        const float* bs = reinterpret_cast<const float*>(smem + (bb ? BS1 : BS0));
        #pragma unroll
        for (int ks = 0; ks < 32; ks += 8) {
            unsigned af[4][4], bf[4][2];
            #pragma unroll
            for (int mf = 0; mf < 4; mf++) {
                int m = m_w + mf*16;
                af[mf][0] = __float_as_uint(as[(m+gid  )*36 + ks+tg  ]);
                af[mf][1] = __float_as_uint(as[(m+gid+8)*36 + ks+tg  ]);
                af[mf][2] = __float_as_uint(as[(m+gid  )*36 + ks+tg+4]);
                af[mf][3] = __float_as_uint(as[(m+gid+8)*36 + ks+tg+4]);
            }
            #pragma unroll
            for (int nf = 0; nf < 4; nf++) {
                int n = n_w + nf*8;
                bf[nf][0] = __float_as_uint(bs[(ks+tg  )*136 + n+gid]);
                bf[nf][1] = __float_as_uint(bs[(ks+tg+4)*136 + n+gid]);
            }
            #pragma unroll
            for (int mf = 0; mf < 4; mf++)
                #pragma unroll
                for (int nf = 0; nf < 4; nf++) {
                    asm volatile(
                        "mma.sync.aligned.m16n8k8.row.col.f32.tf32.tf32.f32 "
                        "{%0,%1,%2,%3}, {%4,%5,%6,%7}, {%8,%9}, {%0,%1,%2,%3};\n"
                        : "+f"(acc[mf][nf][0]), "+f"(acc[mf][nf][1]),
                          "+f"(acc[mf][nf][2]), "+f"(acc[mf][nf][3])
                        : "r"(af[mf][0]), "r"(af[mf][1]), "r"(af[mf][2]), "r"(af[mf][3]),
                          "r"(bf[nf][0]), "r"(bf[nf][1]));
                }
        }
        __syncthreads();
    }

    #pragma unroll
    for (int mf = 0; mf < 4; mf++) {
        #pragma unroll
        for (int nf = 0; nf < 4; nf++) {
            int r0 = row0 + m_w + mf*16 + gid;
            int c0 = col0 + n_w + nf*8 + tg*2;
            float b0 = bias[c0], b1 = bias[c0+1];
            #pragma unroll
            for (int half = 0; half < 2; half++) {
                int r = r0 + half*8;
                if (r < M) {
                    float v0 = acc[mf][nf][half*2+0] + b0;
                    float v1 = acc[mf][nf][half*2+1] + b1;
                    if (EPI == 1) {
                        float2 rv = *reinterpret_cast<const float2*>(res + (size_t)r*Nc + c0);
                        v0 += rv.x; v1 += rv.y;
                    }
                    if (EPI == 2) {
                        v0 = 0.5f * v0 * (1.0f + erff(v0 * 0.7071067811865475f));
                        v1 = 0.5f * v1 * (1.0f + erff(v1 * 0.7071067811865475f));
                    }
                    if (ROUND) { v0 = rtf(v0); v1 = rtf(v1); }
                    *reinterpret_cast<float2*>(C + (size_t)r*Nc + c0) = make_float2(v0, v1);
                }
            }
        }
    }
}

// ===== mma.sync attention GEMMs over fused qkv buffer =====
// MODE 1: S[z,i,j] = 0.125*q_i.k_j (K=HD)    MODE 2: O = S@V (K=N_, rounded out)
template<int BM, int BN, int WM, int WN, int MODE>
__global__ __launch_bounds__((BM/WM)*(BN/WN)*32) void mma_gemm(
        const float* __restrict__ A, const float* __restrict__ Bm,
        float* __restrict__ C, int K) {
    constexpr int BK = 16;
    constexpr int WARPS_N = BN / WN;
    constexpr int NT = (BM/WM) * (BN/WN) * 32;
    constexpr int MFRAG = WM / 16;
    constexpr int NFRAG = WN / 8;
    constexpr int LA4 = (MODE == 2) ? 0 : (BM*BK/4) / NT;
    constexpr int LAS = (MODE == 2) ? (BM*BK) / NT : 0;
    constexpr int LB4 = (BK*BN/4) / NT;

    __shared__ unsigned As[BM][BK + 4];
    __shared__ unsigned Bs[BK][BN + 8];

    int tid = threadIdx.x;
    int wid = tid >> 5, lane = tid & 31;
    int gid = lane >> 2, tg = lane & 3;
    int m_w = (wid / WARPS_N) * WM;
    int n_w = (wid % WARPS_N) * WN;
    int row0 = blockIdx.y * BM, col0 = blockIdx.x * BN;
    int z = blockIdx.z;
    int zb = z / NH_, zh = z % NH_;

    const float* Ab; const float* Bb;
    int lda;
    if constexpr (MODE == 1) { Ab = A + (size_t)(zb*N_)*QD_ + zh*HD_; lda = QD_;
                               Bb = A + (size_t)(zb*N_)*QD_ + D_ + zh*HD_; }
    else                     { Ab = A + (size_t)z*N_*N_; lda = N_;
                               Bb = Bm + (size_t)(zb*N_)*QD_ + 2*D_ + zh*HD_; }

    float acc[MFRAG][NFRAG][4] = {};
    float4 ra[(LA4 > 0) ? LA4 : 1];
    float  ras[(LAS > 0) ? LAS : 1];
    float4 rb[LB4];

    auto load_g = [&](int kt) {
        if constexpr (MODE != 2) {
            #pragma unroll
            for (int p = 0; p < LA4; p++) {
                int idx = tid + p*NT;
                int r = idx >> 2, k4 = idx & 3;
                int gr = row0 + r;
                ra[p] = (gr < N_) ? *reinterpret_cast<const float4*>(Ab + (size_t)gr*lda + kt + k4*4)
                                  : make_float4(0.f, 0.f, 0.f, 0.f);
            }
        } else {
            #pragma unroll
            for (int p = 0; p < LAS; p++) {
                int idx = tid + p*NT;
                int r = idx >> 4, kk = idx & 15;
                int gr = row0 + r;
                ras[p] = (gr < N_ && kt + kk < K) ? Ab[(size_t)gr*lda + kt + kk] : 0.f;
            }
        }
        if constexpr (MODE == 1) {
            #pragma unroll
            for (int p = 0; p < LB4; p++) {
                int idx = tid + p*NT;
                int n = idx >> 2, k4 = idx & 3;
                int gc = col0 + n;
                rb[p] = (gc < N_) ? *reinterpret_cast<const float4*>(Bb + (size_t)gc*QD_ + kt + k4*4)
                                  : make_float4(0.f, 0.f, 0.f, 0.f);
            }
        } else {
            #pragma unroll
            for (int p = 0; p < LB4; p++) {
                int idx = tid + p*NT;
                int kk = idx / (BN/4), n4 = idx % (BN/4);
                rb[p] = (kt + kk < K) ? *reinterpret_cast<const float4*>(Bb + (size_t)(kt+kk)*QD_ + n4*4)
                                      : make_float4(0.f, 0.f, 0.f, 0.f);
            }
        }
    };

    auto store_s = [&]() {
        if constexpr (MODE != 2) {
            #pragma unroll
            for (int p = 0; p < LA4; p++) {
                int idx = tid + p*NT;
                int r = idx >> 2, k4 = idx & 3;
                As[r][k4*4+0] = __float_as_uint(ra[p].x);
                As[r][k4*4+1] = __float_as_uint(ra[p].y);
                As[r][k4*4+2] = __float_as_uint(ra[p].z);
                As[r][k4*4+3] = __float_as_uint(ra[p].w);
            }
        } else {
            #pragma unroll
            for (int p = 0; p < LAS; p++) {
                int idx = tid + p*NT;
                int r = idx >> 4, kk = idx & 15;
                As[r][kk] = __float_as_uint(ras[p]);
            }
        }
        if constexpr (MODE == 1) {
            #pragma unroll
            for (int p = 0; p < LB4; p++) {
                int idx = tid + p*NT;
                int n = idx >> 2, k4 = idx & 3;
                Bs[k4*4+0][n] = __float_as_uint(rb[p].x);
                Bs[k4*4+1][n] = __float_as_uint(rb[p].y);
                Bs[k4*4+2][n] = __float_as_uint(rb[p].z);
                Bs[k4*4+3][n] = __float_as_uint(rb[p].w);
            }
        } else {
            #pragma unroll
            for (int p = 0; p < LB4; p++) {
                int idx = tid + p*NT;
                int kk = idx / (BN/4), n4 = idx % (BN/4);
                uint4 u = make_uint4(__float_as_uint(rb[p].x), __float_as_uint(rb[p].y),
                                     __float_as_uint(rb[p].z), __float_as_uint(rb[p].w));
                *reinterpret_cast<uint4*>(&Bs[kk][n4*4]) = u;
            }
        }
    };

    int KT = (K + BK - 1) / BK;
    load_g(0);
    store_s();
    for (int t = 0; t < KT; t++) {
        __syncthreads();
        if (t + 1 < KT) load_g((t+1)*BK);
        #pragma unroll
        for (int ks = 0; ks < BK; ks += 8) {
            unsigned af[MFRAG][4], bf[NFRAG][2];
            #pragma unroll
            for (int mf = 0; mf < MFRAG; mf++) {
                int m = m_w + mf*16;
                af[mf][0] = As[m + gid    ][ks + tg    ];
                af[mf][1] = As[m + gid + 8][ks + tg    ];
                af[mf][2] = As[m + gid    ][ks + tg + 4];
                af[mf][3] = As[m + gid + 8][ks + tg + 4];
            }
            #pragma unroll
            for (int nf = 0; nf < NFRAG; nf++) {
                int n = n_w + nf*8;
                bf[nf][0] = Bs[ks + tg    ][n + gid];
                bf[nf][1] = Bs[ks + tg + 4][n + gid];
            }
            #pragma unroll
            for (int mf = 0; mf < MFRAG; mf++)
                #pragma unroll
                for (int nf = 0; nf < NFRAG; nf++) {
                    asm volatile(
                        "mma.sync.aligned.m16n8k8.row.col.f32.tf32.tf32.f32 "
                        "{%0,%1,%2,%3}, {%4,%5,%6,%7}, {%8,%9}, {%0,%1,%2,%3};\n"
                        : "+f"(acc[mf][nf][0]), "+f"(acc[mf][nf][1]),
                          "+f"(acc[mf][nf][2]), "+f"(acc[mf][nf][3])
                        : "r"(af[mf][0]), "r"(af[mf][1]), "r"(af[mf][2]), "r"(af[mf][3]),
                          "r"(bf[nf][0]), "r"(bf[nf][1]));
                }
        }
        __syncthreads();
        if (t + 1 < KT) store_s();
    }

    #pragma unroll
    for (int mf = 0; mf < MFRAG; mf++)
        #pragma unroll
        for (int nf = 0; nf < NFRAG; nf++) {
            int rbase = row0 + m_w + mf*16 + gid;
            int cbase = col0 + n_w + nf*8 + tg*2;
            #pragma unroll
            for (int e = 0; e < 4; e++) {
                int r = rbase + (e >> 1) * 8;
                int c = cbase + (e & 1);
                float v = acc[mf][nf][e];
                if constexpr (MODE == 1) {
                    if (r < N_ && c < N_) C[((size_t)z*N_ + r)*N_ + c] = v * 0.125f;
                } else {
                    if (r < N_) C[((size_t)(zb*N_ + r))*D_ + zh*HD_ + c] = rtf(v);
                }
            }
        }
}

// ===== Head =====
__global__ void head_kernel(const float* __restrict__ y, const float* __restrict__ hw,
                            const float* __restrict__ hb, float* __restrict__ out) {
    __shared__ float rowv[D_];
    int b = blockIdx.x;
    int tid = threadIdx.x;
    for (int c = tid; c < D_; c += 256) rowv[c] = y[((size_t)(b*N_))*D_ + c];
    __syncthreads();
    for (int c = tid; c < NCLS_; c += 256) {
        float s = hb[c];
        for (int d = 0; d < D_; d++) s = fmaf(rowv[d], hw[(size_t)d*NCLS_ + c], s);
        out[b*NCLS_ + c] = s;
    }
}

extern "C" void kernel_launch(void* const* d_in, const int* in_sizes, int n_in,
                              void* d_out, int out_size) {
    (void)in_sizes; (void)n_in; (void)out_size;
    const float* x       = (const float*)d_in[0];
    const float* proj_w  = (const float*)d_in[1];
    const float* proj_b  = (const float*)d_in[2];
    const float* cls_emb = (const float*)d_in[3];
    const float* pos_emb = (const float*)d_in[4];
    const float* ln1_g   = (const float*)d_in[5];
    const float* ln1_b   = (const float*)d_in[6];
    const float* qw = (const float*)d_in[7];
    const float* qb = (const float*)d_in[8];
    const float* kw = (const float*)d_in[9];
    const float* kb = (const float*)d_in[10];
    const float* vw = (const float*)d_in[11];
    const float* vb = (const float*)d_in[12];
    const float* ow = (const float*)d_in[13];
    const float* ob = (const float*)d_in[14];
    const float* ln2_g = (const float*)d_in[15];
    const float* ln2_b = (const float*)d_in[16];
    const float* fcw = (const float*)d_in[17];
    const float* fcb = (const float*)d_in[18];
    const float* pw  = (const float*)d_in[19];
    const float* pb  = (const float*)d_in[20];
    const float* lnf_g = (const float*)d_in[21];
    const float* lnf_b = (const float*)d_in[22];
    const float* head_w = (const float*)d_in[23];
    const float* head_b = (const float*)d_in[24];
    float* out = (float*)d_out;

    float *t_p, *h_p, *y_p, *qkv_p, *o_p, *m_p, *s_p;
    float *qkvw, *qkvb, *oww, *fcww, *pww, *projww;
    cudaGetSymbolAddress((void**)&t_p, g_t);
    cudaGetSymbolAddress((void**)&h_p, g_h);
    cudaGetSymbolAddress((void**)&y_p, g_y);
    cudaGetSymbolAddress((void**)&qkv_p, g_qkv);
    cudaGetSymbolAddress((void**)&o_p, g_o);
    cudaGetSymbolAddress((void**)&m_p, g_m);
    cudaGetSymbolAddress((void**)&s_p, g_s);
    cudaGetSymbolAddress((void**)&qkvw, g_qkvw);
    cudaGetSymbolAddress((void**)&qkvb, g_qkvb);
    cudaGetSymbolAddress((void**)&oww, g_oww);
    cudaGetSymbolAddress((void**)&fcww, g_fcww);
    cudaGetSymbolAddress((void**)&pww, g_pww);
    cudaGetSymbolAddress((void**)&projww, g_projww);

    cudaFuncSetAttribute(tf32_gemm<0,0>, cudaFuncAttributeMaxDynamicSharedMemorySize, GA_SMEM);
    cudaFuncSetAttribute(tf32_gemm<0,1>, cudaFuncAttributeMaxDynamicSharedMemorySize, GA_SMEM);
    cudaFuncSetAttribute(tf32_gemm<1,0>, cudaFuncAttributeMaxDynamicSharedMemorySize, GA_SMEM);
    cudaFuncSetAttribute(tf32_gemm<2,1>, cudaFuncAttributeMaxDynamicSharedMemorySize, GA_SMEM);

    // ---- Weight prep (tf32 round copies, qkv fusion) ----
    qkv_concat_w<<<(L_*D_*QD_ + 255)/256, 256>>>(qw, kw, vw, qkvw);
    qkv_concat_b<<<(L_*QD_ + 255)/256, 256>>>(qb, kb, vb, qkvb);
    round_copy<<<(L_*D_*D_ + 255)/256, 256>>>(ow, oww, L_*D_*D_);
    round_copy<<<(L_*D_*MLP_ + 255)/256, 256>>>(fcw, fcww, L_*D_*MLP_);
    round_copy<<<(L_*MLP_*D_ + 255)/256, 256>>>(pw, pww, L_*MLP_*D_);
    round_copy<<<(D_*D_ + 255)/256, 256>>>(proj_w, projww, D_*D_);

    // ---- Patch embed ----
    patchify_kernel<<<(B_*NP_*D_ + 255)/256, 256>>>(x);
    tf32_gemm<0,0><<<dim3(D_/128, PROWS/128), 256, GA_SMEM>>>(
        t_p, projww, proj_b, nullptr, y_p, PROWS, D_, D_);
    assemble_kernel<<<(MROWS*D_ + 255)/256, 256>>>(cls_emb, pos_emb);

    const int gMr = (MROWS + 127) / 128;           // 37
    const dim3 gQKV(QD_/128, gMr);                 // 18 x 37
    const dim3 gD(D_/128, gMr);                    // 6 x 37
    const dim3 gF1(MLP_/128, gMr);                 // 24 x 37
    const int nT128 = (N_ + 127) / 128;            // 5
    const dim3 gS(nT128, nT128, B_*NH_);
    const dim3 gAV(1, nT128, B_*NH_);
    const int lnB = (MROWS + 7) / 8;
    const int smB = (B_*NH_*N_) / 8;

    for (int l = 0; l < L_; l++) {
        float* qkvw_l = qkvw + (size_t)l*D_*QD_;
        float* oww_l  = oww  + (size_t)l*D_*D_;
        float* fcww_l = fcww + (size_t)l*D_*MLP_;
        float* pww_l  = pww  + (size_t)l*MLP_*D_;

        ln_kernel<<<lnB, 256>>>(h_p, y_p, ln1_g + l*D_, ln1_b + l*D_);
        tf32_gemm<0,1><<<gQKV, 256, GA_SMEM>>>(y_p, qkvw_l, qkvb + l*QD_, nullptr,
                                               qkv_p, MROWS, QD_, D_);

        mma_gemm<128,128,64,32,1><<<gS, 256>>>(qkv_p, nullptr, s_p, HD_);
        softmax_kernel<<<smB, 256>>>(s_p);
        mma_gemm<128,64,32,32,2><<<gAV, 256>>>(s_p, qkv_p, o_p, N_);

        tf32_gemm<1,0><<<gD, 256, GA_SMEM>>>(o_p, oww_l, ob + l*D_, h_p, h_p, MROWS, D_, D_);

        ln_kernel<<<lnB, 256>>>(h_p, y_p, ln2_g + l*D_, ln2_b + l*D_);
        tf32_gemm<2,1><<<gF1, 256, GA_SMEM>>>(y_p, fcww_l, fcb + l*MLP_, nullptr,
                                              m_p, MROWS, MLP_, D_);
        tf32_gemm<1,0><<<gD, 256, GA_SMEM>>>(m_p, pww_l, pb + l*D_, h_p, h_p, MROWS, D_, MLP_);
    }

    ln_kernel<<<lnB, 256>>>(h_p, y_p, lnf_g, lnf_b);
    head_kernel<<<B_, 256>>>(y_p, head_w, head_b, out);
}

// round 7
// speedup vs baseline: 4.7602x; 1.1882x over previous
#include <cuda_runtime.h>
#include <math.h>
#include <stdint.h>

// ===== Model config =====
#define B_   8
#define C_   3
#define H_   384
#define W_   384
#define P_   16
#define GH_  24
#define GW_  24
#define NP_  576
#define N_   577
#define D_   768
#define NH_  12
#define HD_  64
#define MLP_ 3072
#define L_   12
#define NCLS_ 1000
#define QD_  (3*D_)          // 2304 fused qkv width

#define MROWS (B_*N_)        // 4616
#define PROWS (B_*NP_)       // 4608

// ===== Scratch =====
__device__ float g_t[B_*NP_*D_];
__device__ float g_h[MROWS*D_];
__device__ float g_y[MROWS*D_];
__device__ float g_qkv[(size_t)MROWS*QD_];
__device__ float g_o[MROWS*D_];
__device__ float g_m[(size_t)MROWS*MLP_];
// tf32-rounded weight copies (natural [K,N] layout for mma B operand)
__device__ float g_qkvw[(size_t)L_*D_*QD_];
__device__ float g_qkvb[L_*QD_];
__device__ float g_oww[(size_t)L_*D_*D_];
__device__ float g_fcww[(size_t)L_*D_*MLP_];
__device__ float g_pww[(size_t)L_*MLP_*D_];
__device__ float g_projww[D_*D_];

__device__ __forceinline__ unsigned f2tf(float f) {
    unsigned u;
    asm("cvt.rna.tf32.f32 %0, %1;" : "=r"(u) : "f"(f));
    return u;
}
__device__ __forceinline__ float rtf(float f) { return __uint_as_float(f2tf(f)); }

__device__ __forceinline__ uint32_t smem_u32(const void* p) {
    uint32_t a;
    asm("{ .reg .u64 t; cvta.to.shared.u64 t, %1; cvt.u32.u64 %0, t; }" : "=r"(a) : "l"(p));
    return a;
}

#define MMA_TF32(acc, a0,a1,a2,a3, b0,b1) \
    asm volatile( \
        "mma.sync.aligned.m16n8k8.row.col.f32.tf32.tf32.f32 " \
        "{%0,%1,%2,%3}, {%4,%5,%6,%7}, {%8,%9}, {%0,%1,%2,%3};\n" \
        : "+f"((acc)[0]), "+f"((acc)[1]), "+f"((acc)[2]), "+f"((acc)[3]) \
        : "r"(a0), "r"(a1), "r"(a2), "r"(a3), "r"(b0), "r"(b1))

// ===== Prep: tf32-round weight copies =====
__global__ void round_copy(const float* __restrict__ in, float* __restrict__ out, int n) {
    int i = blockIdx.x * 256 + threadIdx.x;
    if (i < n) out[i] = rtf(in[i]);
}
__global__ void qkv_concat_w(const float* __restrict__ qw, const float* __restrict__ kw,
                             const float* __restrict__ vw, float* __restrict__ dst) {
    int i = blockIdx.x * 256 + threadIdx.x;
    if (i >= L_*D_*QD_) return;
    int j = i % QD_;
    int lk = i / QD_;
    int sel = j / D_, jj = j % D_;
    const float* src = (sel == 0) ? qw : (sel == 1) ? kw : vw;
    dst[i] = rtf(src[(size_t)lk * D_ + jj]);
}
__global__ void qkv_concat_b(const float* __restrict__ qb, const float* __restrict__ kb,
                             const float* __restrict__ vb, float* __restrict__ dst) {
    int i = blockIdx.x * 256 + threadIdx.x;
    if (i >= L_*QD_) return;
    int j = i % QD_, l = i / QD_;
    int sel = j / D_, jj = j % D_;
    const float* src = (sel == 0) ? qb : (sel == 1) ? kb : vb;
    dst[i] = src[l*D_ + jj];
}

// ===== Patchify (exact reference order), tf32-rounded out =====
__global__ void patchify_kernel(const float* __restrict__ x) {
    int idx = blockIdx.x * blockDim.x + threadIdx.x;
    if (idx >= B_*NP_*D_) return;
    const int BLK = B_*C_*GH_*GW_*P_;
    int p1 = idx / BLK;
    int r  = idx % BLK;
    int m  = r >> 4;
    int p2 = r & 15;
    int gw = m % GW_;  int m2 = m / GW_;
    int gh = m2 % GH_; int m3 = m2 / GH_;
    int c  = m3 % C_;  int bx = m3 / C_;
    g_t[idx] = rtf(x[(((size_t)(bx*C_ + c)*H_) + gh*P_ + p1)*W_ + gw*P_ + p2]);
}

__global__ void assemble_kernel(const float* __restrict__ cls, const float* __restrict__ pos) {
    int idx = blockIdx.x * blockDim.x + threadIdx.x;
    if (idx >= MROWS*D_) return;
    int d  = idx % D_;
    int rn = idx / D_;
    int n  = rn % N_;
    int b  = rn / N_;
    float v = (n == 0) ? cls[d] : g_y[((size_t)(b*NP_ + n - 1))*D_ + d];
    g_h[idx] = v + pos[n*D_ + d];
}

// ===== LayerNorm: warp per row, tf32-rounded output =====
__global__ __launch_bounds__(256) void ln_kernel(const float* __restrict__ in, float* __restrict__ out,
                          const float* __restrict__ g, const float* __restrict__ bb) {
    int wid = threadIdx.x >> 5, lane = threadIdx.x & 31;
    int row = blockIdx.x * 8 + wid;
    if (row >= MROWS) return;
    const float* p = in + (size_t)row * D_;
    float v[24];
    float s = 0.f;
    #pragma unroll
    for (int i = 0; i < 24; i++) { v[i] = p[lane + i*32]; s += v[i]; }
    #pragma unroll
    for (int o = 16; o > 0; o >>= 1) s += __shfl_xor_sync(0xffffffffu, s, o);
    float mean = s * (1.0f / D_);
    float vs = 0.f;
    #pragma unroll
    for (int i = 0; i < 24; i++) { float dx = v[i] - mean; vs += dx*dx; }
    #pragma unroll
    for (int o = 16; o > 0; o >>= 1) vs += __shfl_xor_sync(0xffffffffu, vs, o);
    float rs = rsqrtf(vs * (1.0f / D_) + 1e-5f);
    float* q = out + (size_t)row * D_;
    #pragma unroll
    for (int i = 0; i < 24; i++) {
        int c = lane + i*32;
        q[c] = rtf((v[i] - mean) * rs * g[c] + bb[c]);
    }
}

// ===== Dense TF32 GEMM (cp.async double-buffered, BM=128 BN=128 BK=32) =====
#define GA_SMEM (2*(128*144) + 2*(32*544))    // 71680 bytes
template<int EPI, int ROUND>
__global__ __launch_bounds__(256) void tf32_gemm(
        const float* __restrict__ A, const float* __restrict__ Bw,
        const float* __restrict__ bias, const float* __restrict__ res,
        float* __restrict__ C, int M, int Nc, int K) {
    extern __shared__ char smem[];
    const uint32_t AS0 = 0, AS1 = 128*144, BS0 = 2*128*144, BS1 = 2*128*144 + 32*544;
    uint32_t sbase = smem_u32(smem);

    int tid = threadIdx.x;
    int wid = tid >> 5, lane = tid & 31;
    int gid = lane >> 2, tg = lane & 3;
    int m_w = (wid >> 2) * 64;
    int n_w = (wid & 3) * 32;
    int row0 = blockIdx.y * 128, col0 = blockIdx.x * 128;

    float acc[4][4][4] = {};

    auto load_stage = [&](int t, int bb) {
        uint32_t abase = sbase + (bb ? AS1 : AS0);
        uint32_t bbase = sbase + (bb ? BS1 : BS0);
        int kt = t << 5;
        #pragma unroll
        for (int p = 0; p < 4; p++) {
            int idx = tid + p*256;
            int r = idx >> 3, c = idx & 7;
            int gr = row0 + r;
            const float* src = A + (size_t)(gr < M ? gr : M-1)*K + kt + c*4;
            unsigned sz = (gr < M) ? 16u : 0u;
            asm volatile("cp.async.ca.shared.global [%0], [%1], 16, %2;" ::
                "r"(abase + r*144 + c*16), "l"(src), "r"(sz));
        }
        #pragma unroll
        for (int p = 0; p < 4; p++) {
            int idx = tid + p*256;
            int r = idx >> 5, c = idx & 31;
            const float* src = Bw + (size_t)(kt + r)*Nc + col0 + c*4;
            asm volatile("cp.async.ca.shared.global [%0], [%1], 16;" ::
                "r"(bbase + r*544 + c*16), "l"(src));
        }
        asm volatile("cp.async.commit_group;");
    };

    int KT = K >> 5;
    load_stage(0, 0);
    for (int t = 0; t < KT; t++) {
        int bb = t & 1;
        if (t + 1 < KT) {
            load_stage(t+1, bb^1);
            asm volatile("cp.async.wait_group 1;");
        } else {
            asm volatile("cp.async.wait_group 0;");
        }
        __syncthreads();
        const float* as = reinterpret_cast<const float*>(smem + (bb ? AS1 : AS0));
        const float* bs = reinterpret_cast<const float*>(smem + (bb ? BS1 : BS0));
        #pragma unroll
        for (int ks = 0; ks < 32; ks += 8) {
            unsigned af[4][4], bf[4][2];
            #pragma unroll
            for (int mf = 0; mf < 4; mf++) {
                int m = m_w + mf*16;
                af[mf][0] = __float_as_uint(as[(m+gid  )*36 + ks+tg  ]);
                af[mf][1] = __float_as_uint(as[(m+gid+8)*36 + ks+tg  ]);
                af[mf][2] = __float_as_uint(as[(m+gid  )*36 + ks+tg+4]);
                af[mf][3] = __float_as_uint(as[(m+gid+8)*36 + ks+tg+4]);
            }
            #pragma unroll
            for (int nf = 0; nf < 4; nf++) {
                int n = n_w + nf*8;
                bf[nf][0] = __float_as_uint(bs[(ks+tg  )*136 + n+gid]);
                bf[nf][1] = __float_as_uint(bs[(ks+tg+4)*136 + n+gid]);
            }
            #pragma unroll
            for (int mf = 0; mf < 4; mf++)
                #pragma unroll
                for (int nf = 0; nf < 4; nf++)
                    MMA_TF32(acc[mf][nf], af[mf][0], af[mf][1], af[mf][2], af[mf][3],
                             bf[nf][0], bf[nf][1]);
        }
        __syncthreads();
    }

    #pragma unroll
    for (int mf = 0; mf < 4; mf++) {
        #pragma unroll
        for (int nf = 0; nf < 4; nf++) {
            int r0 = row0 + m_w + mf*16 + gid;
            int c0 = col0 + n_w + nf*8 + tg*2;
            float b0 = bias[c0], b1 = bias[c0+1];
            #pragma unroll
            for (int half = 0; half < 2; half++) {
                int r = r0 + half*8;
                if (r < M) {
                    float v0 = acc[mf][nf][half*2+0] + b0;
                    float v1 = acc[mf][nf][half*2+1] + b1;
                    if (EPI == 1) {
                        float2 rv = *reinterpret_cast<const float2*>(res + (size_t)r*Nc + c0);
                        v0 += rv.x; v1 += rv.y;
                    }
                    if (EPI == 2) {
                        v0 = 0.5f * v0 * (1.0f + erff(v0 * 0.7071067811865475f));
                        v1 = 0.5f * v1 * (1.0f + erff(v1 * 0.7071067811865475f));
                    }
                    if (ROUND) { v0 = rtf(v0); v1 = rtf(v1); }
                    *reinterpret_cast<float2*>(C + (size_t)r*Nc + c0) = make_float2(v0, v1);
                }
            }
        }
    }
}

// ===== Fused flash attention =====
// Per block: 64 Q rows of one (b,h); loop over 10 J-tiles of 64.
// Q in registers (A-frags, x0.125 folded), K/V/P in smem, online softmax in regs.
// smem: Ks[64][68] @0, Vs[64][72] @17408, Ps[64][68] @35840 -> total 53248 bytes
#define FA_SMEM 53248
__global__ __launch_bounds__(128) void flash_attn(
        const float* __restrict__ qkv, float* __restrict__ o) {
    extern __shared__ float fs[];
    float* Ks = fs;                  // stride 68
    float* Vs = fs + 17408/4;        // stride 72
    float* Ps = fs + 35840/4;        // stride 68

    int tid = threadIdx.x;
    int wid = tid >> 5, lane = tid & 31;
    int gid = lane >> 2, tg = lane & 3;
    int z = blockIdx.y;
    int zb = z / NH_, zh = z % NH_;
    int i0 = blockIdx.x * 64;
    int r_w = wid * 16;

    // ---- stage Q tile into Ps, pick up A-frags into registers ----
    #pragma unroll
    for (int p = 0; p < 8; p++) {
        int idx = tid + p*128;
        int r = idx >> 4, c4 = idx & 15;
        int gr = i0 + r; if (gr > N_-1) gr = N_-1;
        float4 v = *reinterpret_cast<const float4*>(
            qkv + (size_t)(zb*N_ + gr)*QD_ + zh*HD_ + c4*4);
        float* dst = Ps + r*68 + c4*4;
        dst[0] = v.x*0.125f; dst[1] = v.y*0.125f; dst[2] = v.z*0.125f; dst[3] = v.w*0.125f;
    }
    __syncthreads();
    unsigned qa[8][4];
    #pragma unroll
    for (int ks = 0; ks < 8; ks++) {
        qa[ks][0] = __float_as_uint(Ps[(r_w+gid  )*68 + ks*8+tg  ]);
        qa[ks][1] = __float_as_uint(Ps[(r_w+gid+8)*68 + ks*8+tg  ]);
        qa[ks][2] = __float_as_uint(Ps[(r_w+gid  )*68 + ks*8+tg+4]);
        qa[ks][3] = __float_as_uint(Ps[(r_w+gid+8)*68 + ks*8+tg+4]);
    }
    __syncthreads();

    float m0 = -1e30f, m1 = -1e30f, l0 = 0.f, l1 = 0.f;
    float oa[8][4] = {};

    for (int jt = 0; jt < 10; jt++) {
        int j0 = jt * 64;
        // ---- load K, V tiles ----
        #pragma unroll
        for (int p = 0; p < 8; p++) {
            int idx = tid + p*128;
            int r = idx >> 4, c4 = idx & 15;
            int gj = j0 + r; if (gj > N_-1) gj = N_-1;
            const float* base = qkv + (size_t)(zb*N_ + gj)*QD_ + zh*HD_ + c4*4;
            float4 kv = *reinterpret_cast<const float4*>(base + D_);
            float4 vv = *reinterpret_cast<const float4*>(base + 2*D_);
            *reinterpret_cast<float4*>(Ks + r*68 + c4*4) = kv;
            *reinterpret_cast<float4*>(Vs + r*72 + c4*4) = vv;
        }
        __syncthreads();

        // ---- scores S = (Q*0.125) @ K^T ----
        float s[8][4] = {};
        #pragma unroll
        for (int ks = 0; ks < 8; ks++) {
            #pragma unroll
            for (int nf = 0; nf < 8; nf++) {
                unsigned b0 = __float_as_uint(Ks[(nf*8+gid)*68 + ks*8+tg  ]);
                unsigned b1 = __float_as_uint(Ks[(nf*8+gid)*68 + ks*8+tg+4]);
                MMA_TF32(s[nf], qa[ks][0], qa[ks][1], qa[ks][2], qa[ks][3], b0, b1);
            }
        }
        // ---- mask padded j ----
        if (j0 + 64 > N_) {
            #pragma unroll
            for (int nf = 0; nf < 8; nf++) {
                int c0 = j0 + nf*8 + tg*2;
                if (c0     >= N_) { s[nf][0] = -1e30f; s[nf][2] = -1e30f; }
                if (c0 + 1 >= N_) { s[nf][1] = -1e30f; s[nf][3] = -1e30f; }
            }
        }
        // ---- online softmax (rows gid and gid+8 of this warp's 16-row slice) ----
        float tm0 = -1e30f, tm1 = -1e30f;
        #pragma unroll
        for (int nf = 0; nf < 8; nf++) {
            tm0 = fmaxf(tm0, fmaxf(s[nf][0], s[nf][1]));
            tm1 = fmaxf(tm1, fmaxf(s[nf][2], s[nf][3]));
        }
        #pragma unroll
        for (int off = 1; off <= 2; off <<= 1) {
            tm0 = fmaxf(tm0, __shfl_xor_sync(0xffffffffu, tm0, off));
            tm1 = fmaxf(tm1, __shfl_xor_sync(0xffffffffu, tm1, off));
        }
        float m0n = fmaxf(m0, tm0), m1n = fmaxf(m1, tm1);
        float a0 = __expf(m0 - m0n), a1 = __expf(m1 - m1n);
        float ps0 = 0.f, ps1 = 0.f;
        #pragma unroll
        for (int nf = 0; nf < 8; nf++) {
            float p0 = __expf(s[nf][0] - m0n);
            float p1 = __expf(s[nf][1] - m0n);
            float p2 = __expf(s[nf][2] - m1n);
            float p3 = __expf(s[nf][3] - m1n);
            ps0 += p0 + p1; ps1 += p2 + p3;
            float* d0 = Ps + (r_w+gid  )*68 + nf*8 + tg*2;
            float* d1 = Ps + (r_w+gid+8)*68 + nf*8 + tg*2;
            d0[0] = rtf(p0); d0[1] = rtf(p1);
            d1[0] = rtf(p2); d1[1] = rtf(p3);
            oa[nf][0] *= a0; oa[nf][1] *= a0;
            oa[nf][2] *= a1; oa[nf][3] *= a1;
        }
        #pragma unroll
        for (int off = 1; off <= 2; off <<= 1) {
            ps0 += __shfl_xor_sync(0xffffffffu, ps0, off);
            ps1 += __shfl_xor_sync(0xffffffffu, ps1, off);
        }
        l0 = l0*a0 + ps0; l1 = l1*a1 + ps1;
        m0 = m0n; m1 = m1n;
        __syncthreads();   // P visible to whole warp? (warp-local but also gate Ks reuse)

        // ---- O += P @ V ----
        #pragma unroll
        for (int ks = 0; ks < 8; ks++) {
            unsigned pa0 = __float_as_uint(Ps[(r_w+gid  )*68 + ks*8+tg  ]);
            unsigned pa1 = __float_as_uint(Ps[(r_w+gid+8)*68 + ks*8+tg  ]);
            unsigned pa2 = __float_as_uint(Ps[(r_w+gid  )*68 + ks*8+tg+4]);
            unsigned pa3 = __float_as_uint(Ps[(r_w+gid+8)*68 + ks*8+tg+4]);
            #pragma unroll
            for (int nf = 0; nf < 8; nf++) {
                unsigned b0 = __float_as_uint(Vs[(ks*8+tg  )*72 + nf*8+gid]);
                unsigned b1 = __float_as_uint(Vs[(ks*8+tg+4)*72 + nf*8+gid]);
                MMA_TF32(oa[nf], pa0, pa1, pa2, pa3, b0, b1);
            }
        }
        __syncthreads();   // done with Ks/Vs/Ps before next tile overwrites
    }

    // ---- normalize + store (tf32-rounded; feeds O-proj GEMM A) ----
    float inv0 = 1.0f / l0, inv1 = 1.0f / l1;
    int gr0 = i0 + r_w + gid, gr1 = gr0 + 8;
    #pragma unroll
    for (int nf = 0; nf < 8; nf++) {
        int col = zh*HD_ + nf*8 + tg*2;
        if (gr0 < N_)
            *reinterpret_cast<float2*>(o + (size_t)(zb*N_ + gr0)*D_ + col) =
                make_float2(rtf(oa[nf][0]*inv0), rtf(oa[nf][1]*inv0));
        if (gr1 < N_)
            *reinterpret_cast<float2*>(o + (size_t)(zb*N_ + gr1)*D_ + col) =
                make_float2(rtf(oa[nf][2]*inv1), rtf(oa[nf][3]*inv1));
    }
}

// ===== Head =====
__global__ void head_kernel(const float* __restrict__ y, const float* __restrict__ hw,
                            const float* __restrict__ hb, float* __restrict__ out) {
    __shared__ float rowv[D_];
    int b = blockIdx.x;
    int tid = threadIdx.x;
    for (int c = tid; c < D_; c += 256) rowv[c] = y[((size_t)(b*N_))*D_ + c];
    __syncthreads();
    for (int c = tid; c < NCLS_; c += 256) {
        float s = hb[c];
        for (int d = 0; d < D_; d++) s = fmaf(rowv[d], hw[(size_t)d*NCLS_ + c], s);
        out[b*NCLS_ + c] = s;
    }
}

extern "C" void kernel_launch(void* const* d_in, const int* in_sizes, int n_in,
                              void* d_out, int out_size) {
    (void)in_sizes; (void)n_in; (void)out_size;
    const float* x       = (const float*)d_in[0];
    const float* proj_w  = (const float*)d_in[1];
    const float* proj_b  = (const float*)d_in[2];
    const float* cls_emb = (const float*)d_in[3];
    const float* pos_emb = (const float*)d_in[4];
    const float* ln1_g   = (const float*)d_in[5];
    const float* ln1_b   = (const float*)d_in[6];
    const float* qw = (const float*)d_in[7];
    const float* qb = (const float*)d_in[8];
    const float* kw = (const float*)d_in[9];
    const float* kb = (const float*)d_in[10];
    const float* vw = (const float*)d_in[11];
    const float* vb = (const float*)d_in[12];
    const float* ow = (const float*)d_in[13];
    const float* ob = (const float*)d_in[14];
    const float* ln2_g = (const float*)d_in[15];
    const float* ln2_b = (const float*)d_in[16];
    const float* fcw = (const float*)d_in[17];
    const float* fcb = (const float*)d_in[18];
    const float* pw  = (const float*)d_in[19];
    const float* pb  = (const float*)d_in[20];
    const float* lnf_g = (const float*)d_in[21];
    const float* lnf_b = (const float*)d_in[22];
    const float* head_w = (const float*)d_in[23];
    const float* head_b = (const float*)d_in[24];
    float* out = (float*)d_out;

    float *t_p, *h_p, *y_p, *qkv_p, *o_p, *m_p;
    float *qkvw, *qkvb, *oww, *fcww, *pww, *projww;
    cudaGetSymbolAddress((void**)&t_p, g_t);
    cudaGetSymbolAddress((void**)&h_p, g_h);
    cudaGetSymbolAddress((void**)&y_p, g_y);
    cudaGetSymbolAddress((void**)&qkv_p, g_qkv);
    cudaGetSymbolAddress((void**)&o_p, g_o);
    cudaGetSymbolAddress((void**)&m_p, g_m);
    cudaGetSymbolAddress((void**)&qkvw, g_qkvw);
    cudaGetSymbolAddress((void**)&qkvb, g_qkvb);
    cudaGetSymbolAddress((void**)&oww, g_oww);
    cudaGetSymbolAddress((void**)&fcww, g_fcww);
    cudaGetSymbolAddress((void**)&pww, g_pww);
    cudaGetSymbolAddress((void**)&projww, g_projww);

    cudaFuncSetAttribute(tf32_gemm<0,0>, cudaFuncAttributeMaxDynamicSharedMemorySize, GA_SMEM);
    cudaFuncSetAttribute(tf32_gemm<0,1>, cudaFuncAttributeMaxDynamicSharedMemorySize, GA_SMEM);
    cudaFuncSetAttribute(tf32_gemm<1,0>, cudaFuncAttributeMaxDynamicSharedMemorySize, GA_SMEM);
    cudaFuncSetAttribute(tf32_gemm<2,1>, cudaFuncAttributeMaxDynamicSharedMemorySize, GA_SMEM);
    cudaFuncSetAttribute(flash_attn, cudaFuncAttributeMaxDynamicSharedMemorySize, FA_SMEM);

    // ---- Weight prep ----
    qkv_concat_w<<<(L_*D_*QD_ + 255)/256, 256>>>(qw, kw, vw, qkvw);
    qkv_concat_b<<<(L_*QD_ + 255)/256, 256>>>(qb, kb, vb, qkvb);
    round_copy<<<(L_*D_*D_ + 255)/256, 256>>>(ow, oww, L_*D_*D_);
    round_copy<<<(L_*D_*MLP_ + 255)/256, 256>>>(fcw, fcww, L_*D_*MLP_);
    round_copy<<<(L_*MLP_*D_ + 255)/256, 256>>>(pw, pww, L_*MLP_*D_);
    round_copy<<<(D_*D_ + 255)/256, 256>>>(proj_w, projww, D_*D_);

    // ---- Patch embed ----
    patchify_kernel<<<(B_*NP_*D_ + 255)/256, 256>>>(x);
    tf32_gemm<0,0><<<dim3(D_/128, PROWS/128), 256, GA_SMEM>>>(
        t_p, projww, proj_b, nullptr, y_p, PROWS, D_, D_);
    assemble_kernel<<<(MROWS*D_ + 255)/256, 256>>>(cls_emb, pos_emb);

    const int gMr = (MROWS + 127) / 128;           // 37
    const dim3 gQKV(QD_/128, gMr);
    const dim3 gD(D_/128, gMr);
    const dim3 gF1(MLP_/128, gMr);
    const dim3 gFA((N_ + 63)/64, B_*NH_);          // 10 x 96
    const int lnB = (MROWS + 7) / 8;

    for (int l = 0; l < L_; l++) {
        float* qkvw_l = qkvw + (size_t)l*D_*QD_;
        float* oww_l  = oww  + (size_t)l*D_*D_;
        float* fcww_l = fcww + (size_t)l*D_*MLP_;
        float* pww_l  = pww  + (size_t)l*MLP_*D_;

        ln_kernel<<<lnB, 256>>>(h_p, y_p, ln1_g + l*D_, ln1_b + l*D_);
        tf32_gemm<0,1><<<gQKV, 256, GA_SMEM>>>(y_p, qkvw_l, qkvb + l*QD_, nullptr,
                                               qkv_p, MROWS, QD_, D_);

        flash_attn<<<gFA, 128, FA_SMEM>>>(qkv_p, o_p);

        tf32_gemm<1,0><<<gD, 256, GA_SMEM>>>(o_p, oww_l, ob + l*D_, h_p, h_p, MROWS, D_, D_);

        ln_kernel<<<lnB, 256>>>(h_p, y_p, ln2_g + l*D_, ln2_b + l*D_);
        tf32_gemm<2,1><<<gF1, 256, GA_SMEM>>>(y_p, fcww_l, fcb + l*MLP_, nullptr,
                                              m_p, MROWS, MLP_, D_);
        tf32_gemm<1,0><<<gD, 256, GA_SMEM>>>(m_p, pww_l, pb + l*D_, h_p, h_p, MROWS, D_, MLP_);
    }

    ln_kernel<<<lnB, 256>>>(h_p, y_p, lnf_g, lnf_b);
    head_kernel<<<B_, 256>>>(y_p, head_w, head_b, out);
}

// round 8
// speedup vs baseline: 4.7668x; 1.0014x over previous
#include <cuda_runtime.h>
#include <math.h>
#include <stdint.h>

// ===== Model config =====
#define B_   8
#define C_   3
#define H_   384
#define W_   384
#define P_   16
#define GH_  24
#define GW_  24
#define NP_  576
#define N_   577
#define D_   768
#define NH_  12
#define HD_  64
#define MLP_ 3072
#define L_   12
#define NCLS_ 1000
#define QD_  (3*D_)          // 2304 fused qkv width

#define MROWS (B_*N_)        // 4616
#define PROWS (B_*NP_)       // 4608

// ===== Scratch =====
__device__ float g_t[B_*NP_*D_];
__device__ float g_h[MROWS*D_];
__device__ float g_y[MROWS*D_];
__device__ float g_qkv[(size_t)MROWS*QD_];
__device__ float g_o[MROWS*D_];
__device__ float g_m[(size_t)MROWS*MLP_];
// tf32-rounded weight copies (natural [K,N] layout for mma B operand)
__device__ float g_qkvw[(size_t)L_*D_*QD_];
__device__ float g_qkvb[L_*QD_];
__device__ float g_oww[(size_t)L_*D_*D_];
__device__ float g_fcww[(size_t)L_*D_*MLP_];
__device__ float g_pww[(size_t)L_*MLP_*D_];
__device__ float g_projww[D_*D_];

__device__ __forceinline__ unsigned f2tf(float f) {
    unsigned u;
    asm("cvt.rna.tf32.f32 %0, %1;" : "=r"(u) : "f"(f));
    return u;
}
__device__ __forceinline__ float rtf(float f) { return __uint_as_float(f2tf(f)); }

__device__ __forceinline__ uint32_t smem_u32(const void* p) {
    uint32_t a;
    asm("{ .reg .u64 t; cvta.to.shared.u64 t, %1; cvt.u32.u64 %0, t; }" : "=r"(a) : "l"(p));
    return a;
}

#define MMA_TF32(acc, a0,a1,a2,a3, b0,b1) \
    asm volatile( \
        "mma.sync.aligned.m16n8k8.row.col.f32.tf32.tf32.f32 " \
        "{%0,%1,%2,%3}, {%4,%5,%6,%7}, {%8,%9}, {%0,%1,%2,%3};\n" \
        : "+f"((acc)[0]), "+f"((acc)[1]), "+f"((acc)[2]), "+f"((acc)[3]) \
        : "r"(a0), "r"(a1), "r"(a2), "r"(a3), "r"(b0), "r"(b1))

// ===== Prep: tf32-round weight copies =====
__global__ void round_copy(const float* __restrict__ in, float* __restrict__ out, int n) {
    int i = blockIdx.x * 256 + threadIdx.x;
    if (i < n) out[i] = rtf(in[i]);
}
__global__ void qkv_concat_w(const float* __restrict__ qw, const float* __restrict__ kw,
                             const float* __restrict__ vw, float* __restrict__ dst) {
    int i = blockIdx.x * 256 + threadIdx.x;
    if (i >= L_*D_*QD_) return;
    int j = i % QD_;
    int lk = i / QD_;
    int sel = j / D_, jj = j % D_;
    const float* src = (sel == 0) ? qw : (sel == 1) ? kw : vw;
    dst[i] = rtf(src[(size_t)lk * D_ + jj]);
}
__global__ void qkv_concat_b(const float* __restrict__ qb, const float* __restrict__ kb,
                             const float* __restrict__ vb, float* __restrict__ dst) {
    int i = blockIdx.x * 256 + threadIdx.x;
    if (i >= L_*QD_) return;
    int j = i % QD_, l = i / QD_;
    int sel = j / D_, jj = j % D_;
    const float* src = (sel == 0) ? qb : (sel == 1) ? kb : vb;
    dst[i] = src[l*D_ + jj];
}

// ===== Patchify (exact reference order), tf32-rounded out =====
__global__ void patchify_kernel(const float* __restrict__ x) {
    int idx = blockIdx.x * blockDim.x + threadIdx.x;
    if (idx >= B_*NP_*D_) return;
    const int BLK = B_*C_*GH_*GW_*P_;
    int p1 = idx / BLK;
    int r  = idx % BLK;
    int m  = r >> 4;
    int p2 = r & 15;
    int gw = m % GW_;  int m2 = m / GW_;
    int gh = m2 % GH_; int m3 = m2 / GH_;
    int c  = m3 % C_;  int bx = m3 / C_;
    g_t[idx] = rtf(x[(((size_t)(bx*C_ + c)*H_) + gh*P_ + p1)*W_ + gw*P_ + p2]);
}

__global__ void assemble_kernel(const float* __restrict__ cls, const float* __restrict__ pos) {
    int idx = blockIdx.x * blockDim.x + threadIdx.x;
    if (idx >= MROWS*D_) return;
    int d  = idx % D_;
    int rn = idx / D_;
    int n  = rn % N_;
    int b  = rn / N_;
    float v = (n == 0) ? cls[d] : g_y[((size_t)(b*NP_ + n - 1))*D_ + d];
    g_h[idx] = v + pos[n*D_ + d];
}

// ===== LayerNorm: warp per row, tf32-rounded output =====
__global__ __launch_bounds__(256) void ln_kernel(const float* __restrict__ in, float* __restrict__ out,
                          const float* __restrict__ g, const float* __restrict__ bb) {
    int wid = threadIdx.x >> 5, lane = threadIdx.x & 31;
    int row = blockIdx.x * 8 + wid;
    if (row >= MROWS) return;
    const float* p = in + (size_t)row * D_;
    float v[24];
    float s = 0.f;
    #pragma unroll
    for (int i = 0; i < 24; i++) { v[i] = p[lane + i*32]; s += v[i]; }
    #pragma unroll
    for (int o = 16; o > 0; o >>= 1) s += __shfl_xor_sync(0xffffffffu, s, o);
    float mean = s * (1.0f / D_);
    float vs = 0.f;
    #pragma unroll
    for (int i = 0; i < 24; i++) { float dx = v[i] - mean; vs += dx*dx; }
    #pragma unroll
    for (int o = 16; o > 0; o >>= 1) vs += __shfl_xor_sync(0xffffffffu, vs, o);
    float rs = rsqrtf(vs * (1.0f / D_) + 1e-5f);
    float* q = out + (size_t)row * D_;
    #pragma unroll
    for (int i = 0; i < 24; i++) {
        int c = lane + i*32;
        q[c] = rtf((v[i] - mean) * rs * g[c] + bb[c]);
    }
}

// ===== Dense TF32 GEMM (cp.async double-buffered, BM=128 BN=128 BK=32) =====
#define GA_SMEM (2*(128*144) + 2*(32*544))    // 71680 bytes
template<int EPI, int ROUND>
__global__ __launch_bounds__(256) void tf32_gemm(
        const float* __restrict__ A, const float* __restrict__ Bw,
        const float* __restrict__ bias, const float* __restrict__ res,
        float* __restrict__ C, int M, int Nc, int K) {
    extern __shared__ char smem[];
    const uint32_t AS0 = 0, AS1 = 128*144, BS0 = 2*128*144, BS1 = 2*128*144 + 32*544;
    uint32_t sbase = smem_u32(smem);

    int tid = threadIdx.x;
    int wid = tid >> 5, lane = tid & 31;
    int gid = lane >> 2, tg = lane & 3;
    int m_w = (wid >> 2) * 64;
    int n_w = (wid & 3) * 32;
    int row0 = blockIdx.y * 128, col0 = blockIdx.x * 128;

    float acc[4][4][4] = {};

    auto load_stage = [&](int t, int bb) {
        uint32_t abase = sbase + (bb ? AS1 : AS0);
        uint32_t bbase = sbase + (bb ? BS1 : BS0);
        int kt = t << 5;
        #pragma unroll
        for (int p = 0; p < 4; p++) {
            int idx = tid + p*256;
            int r = idx >> 3, c = idx & 7;
            int gr = row0 + r;
            const float* src = A + (size_t)(gr < M ? gr : M-1)*K + kt + c*4;
            unsigned sz = (gr < M) ? 16u : 0u;
            asm volatile("cp.async.ca.shared.global [%0], [%1], 16, %2;" ::
                "r"(abase + r*144 + c*16), "l"(src), "r"(sz));
        }
        #pragma unroll
        for (int p = 0; p < 4; p++) {
            int idx = tid + p*256;
            int r = idx >> 5, c = idx & 31;
            const float* src = Bw + (size_t)(kt + r)*Nc + col0 + c*4;
            asm volatile("cp.async.ca.shared.global [%0], [%1], 16;" ::
                "r"(bbase + r*544 + c*16), "l"(src));
        }
        asm volatile("cp.async.commit_group;");
    };

    int KT = K >> 5;
    load_stage(0, 0);
    for (int t = 0; t < KT; t++) {
        int bb = t & 1;
        if (t + 1 < KT) {
            load_stage(t+1, bb^1);
            asm volatile("cp.async.wait_group 1;");
        } else {
            asm volatile("cp.async.wait_group 0;");
        }
        __syncthreads();
        const float* as = reinterpret_cast<const float*>(smem + (bb ? AS1 : AS0));
        const float* bs = reinterpret_cast<const float*>(smem + (bb ? BS1 : BS0));
        #pragma unroll
        for (int ks = 0; ks < 32; ks += 8) {
            unsigned af[4][4], bf[4][2];
            #pragma unroll
            for (int mf = 0; mf < 4; mf++) {
                int m = m_w + mf*16;
                af[mf][0] = __float_as_uint(as[(m+gid  )*36 + ks+tg  ]);
                af[mf][1] = __float_as_uint(as[(m+gid+8)*36 + ks+tg  ]);
                af[mf][2] = __float_as_uint(as[(m+gid  )*36 + ks+tg+4]);
                af[mf][3] = __float_as_uint(as[(m+gid+8)*36 + ks+tg+4]);
            }
            #pragma unroll
            for (int nf = 0; nf < 4; nf++) {
                int n = n_w + nf*8;
                bf[nf][0] = __float_as_uint(bs[(ks+tg  )*136 + n+gid]);
                bf[nf][1] = __float_as_uint(bs[(ks+tg+4)*136 + n+gid]);
            }
            #pragma unroll
            for (int mf = 0; mf < 4; mf++)
                #pragma unroll
                for (int nf = 0; nf < 4; nf++)
                    MMA_TF32(acc[mf][nf], af[mf][0], af[mf][1], af[mf][2], af[mf][3],
                             bf[nf][0], bf[nf][1]);
        }
        __syncthreads();
    }

    #pragma unroll
    for (int mf = 0; mf < 4; mf++) {
        #pragma unroll
        for (int nf = 0; nf < 4; nf++) {
            int r0 = row0 + m_w + mf*16 + gid;
            int c0 = col0 + n_w + nf*8 + tg*2;
            float b0 = bias[c0], b1 = bias[c0+1];
            #pragma unroll
            for (int half = 0; half < 2; half++) {
                int r = r0 + half*8;
                if (r < M) {
                    float v0 = acc[mf][nf][half*2+0] + b0;
                    float v1 = acc[mf][nf][half*2+1] + b1;
                    if (EPI == 1) {
                        float2 rv = *reinterpret_cast<const float2*>(res + (size_t)r*Nc + c0);
                        v0 += rv.x; v1 += rv.y;
                    }
                    if (EPI == 2) {
                        v0 = 0.5f * v0 * (1.0f + erff(v0 * 0.7071067811865475f));
                        v1 = 0.5f * v1 * (1.0f + erff(v1 * 0.7071067811865475f));
                    }
                    if (ROUND) { v0 = rtf(v0); v1 = rtf(v1); }
                    *reinterpret_cast<float2*>(C + (size_t)r*Nc + c0) = make_float2(v0, v1);
                }
            }
        }
    }
}

// ===== Fused flash attention =====
// Per block: 64 Q rows of one (b,h); loop over 10 J-tiles of 64.
// Q in registers (A-frags, x0.125 folded), K/V/P in smem, online softmax in regs.
// smem: Ks[64][68] @0, Vs[64][72] @17408, Ps[64][68] @35840 -> total 53248 bytes
#define FA_SMEM 53248
__global__ __launch_bounds__(128) void flash_attn(
        const float* __restrict__ qkv, float* __restrict__ o) {
    extern __shared__ float fs[];
    float* Ks = fs;                  // stride 68
    float* Vs = fs + 17408/4;        // stride 72
    float* Ps = fs + 35840/4;        // stride 68

    int tid = threadIdx.x;
    int wid = tid >> 5, lane = tid & 31;
    int gid = lane >> 2, tg = lane & 3;
    int z = blockIdx.y;
    int zb = z / NH_, zh = z % NH_;
    int i0 = blockIdx.x * 64;
    int r_w = wid * 16;

    // ---- stage Q tile into Ps, pick up A-frags into registers ----
    #pragma unroll
    for (int p = 0; p < 8; p++) {
        int idx = tid + p*128;
        int r = idx >> 4, c4 = idx & 15;
        int gr = i0 + r; if (gr > N_-1) gr = N_-1;
        float4 v = *reinterpret_cast<const float4*>(
            qkv + (size_t)(zb*N_ + gr)*QD_ + zh*HD_ + c4*4);
        float* dst = Ps + r*68 + c4*4;
        dst[0] = v.x*0.125f; dst[1] = v.y*0.125f; dst[2] = v.z*0.125f; dst[3] = v.w*0.125f;
    }
    __syncthreads();
    unsigned qa[8][4];
    #pragma unroll
    for (int ks = 0; ks < 8; ks++) {
        qa[ks][0] = __float_as_uint(Ps[(r_w+gid  )*68 + ks*8+tg  ]);
        qa[ks][1] = __float_as_uint(Ps[(r_w+gid+8)*68 + ks*8+tg  ]);
        qa[ks][2] = __float_as_uint(Ps[(r_w+gid  )*68 + ks*8+tg+4]);
        qa[ks][3] = __float_as_uint(Ps[(r_w+gid+8)*68 + ks*8+tg+4]);
    }
    __syncthreads();

    float m0 = -1e30f, m1 = -1e30f, l0 = 0.f, l1 = 0.f;
    float oa[8][4] = {};

    for (int jt = 0; jt < 10; jt++) {
        int j0 = jt * 64;
        // ---- load K, V tiles ----
        #pragma unroll
        for (int p = 0; p < 8; p++) {
            int idx = tid + p*128;
            int r = idx >> 4, c4 = idx & 15;
            int gj = j0 + r; if (gj > N_-1) gj = N_-1;
            const float* base = qkv + (size_t)(zb*N_ + gj)*QD_ + zh*HD_ + c4*4;
            float4 kv = *reinterpret_cast<const float4*>(base + D_);
            float4 vv = *reinterpret_cast<const float4*>(base + 2*D_);
            *reinterpret_cast<float4*>(Ks + r*68 + c4*4) = kv;
            *reinterpret_cast<float4*>(Vs + r*72 + c4*4) = vv;
        }
        __syncthreads();

        // ---- scores S = (Q*0.125) @ K^T ----
        float s[8][4] = {};
        #pragma unroll
        for (int ks = 0; ks < 8; ks++) {
            #pragma unroll
            for (int nf = 0; nf < 8; nf++) {
                unsigned b0 = __float_as_uint(Ks[(nf*8+gid)*68 + ks*8+tg  ]);
                unsigned b1 = __float_as_uint(Ks[(nf*8+gid)*68 + ks*8+tg+4]);
                MMA_TF32(s[nf], qa[ks][0], qa[ks][1], qa[ks][2], qa[ks][3], b0, b1);
            }
        }
        // ---- mask padded j ----
        if (j0 + 64 > N_) {
            #pragma unroll
            for (int nf = 0; nf < 8; nf++) {
                int c0 = j0 + nf*8 + tg*2;
                if (c0     >= N_) { s[nf][0] = -1e30f; s[nf][2] = -1e30f; }
                if (c0 + 1 >= N_) { s[nf][1] = -1e30f; s[nf][3] = -1e30f; }
            }
        }
        // ---- online softmax (rows gid and gid+8 of this warp's 16-row slice) ----
        float tm0 = -1e30f, tm1 = -1e30f;
        #pragma unroll
        for (int nf = 0; nf < 8; nf++) {
            tm0 = fmaxf(tm0, fmaxf(s[nf][0], s[nf][1]));
            tm1 = fmaxf(tm1, fmaxf(s[nf][2], s[nf][3]));
        }
        #pragma unroll
        for (int off = 1; off <= 2; off <<= 1) {
            tm0 = fmaxf(tm0, __shfl_xor_sync(0xffffffffu, tm0, off));
            tm1 = fmaxf(tm1, __shfl_xor_sync(0xffffffffu, tm1, off));
        }
        float m0n = fmaxf(m0, tm0), m1n = fmaxf(m1, tm1);
        float a0 = __expf(m0 - m0n), a1 = __expf(m1 - m1n);
        float ps0 = 0.f, ps1 = 0.f;
        #pragma unroll
        for (int nf = 0; nf < 8; nf++) {
            float p0 = __expf(s[nf][0] - m0n);
            float p1 = __expf(s[nf][1] - m0n);
            float p2 = __expf(s[nf][2] - m1n);
            float p3 = __expf(s[nf][3] - m1n);
            ps0 += p0 + p1; ps1 += p2 + p3;
            float* d0 = Ps + (r_w+gid  )*68 + nf*8 + tg*2;
            float* d1 = Ps + (r_w+gid+8)*68 + nf*8 + tg*2;
            d0[0] = rtf(p0); d0[1] = rtf(p1);
            d1[0] = rtf(p2); d1[1] = rtf(p3);
            oa[nf][0] *= a0; oa[nf][1] *= a0;
            oa[nf][2] *= a1; oa[nf][3] *= a1;
        }
        #pragma unroll
        for (int off = 1; off <= 2; off <<= 1) {
            ps0 += __shfl_xor_sync(0xffffffffu, ps0, off);
            ps1 += __shfl_xor_sync(0xffffffffu, ps1, off);
        }
        l0 = l0*a0 + ps0; l1 = l1*a1 + ps1;
        m0 = m0n; m1 = m1n;
        __syncthreads();   // P visible to whole warp? (warp-local but also gate Ks reuse)

        // ---- O += P @ V ----
        #pragma unroll
        for (int ks = 0; ks < 8; ks++) {
            unsigned pa0 = __float_as_uint(Ps[(r_w+gid  )*68 + ks*8+tg  ]);
            unsigned pa1 = __float_as_uint(Ps[(r_w+gid+8)*68 + ks*8+tg  ]);
            unsigned pa2 = __float_as_uint(Ps[(r_w+gid  )*68 + ks*8+tg+4]);
            unsigned pa3 = __float_as_uint(Ps[(r_w+gid+8)*68 + ks*8+tg+4]);
            #pragma unroll
            for (int nf = 0; nf < 8; nf++) {
                unsigned b0 = __float_as_uint(Vs[(ks*8+tg  )*72 + nf*8+gid]);
                unsigned b1 = __float_as_uint(Vs[(ks*8+tg+4)*72 + nf*8+gid]);
                MMA_TF32(oa[nf], pa0, pa1, pa2, pa3, b0, b1);
            }
        }
        __syncthreads();   // done with Ks/Vs/Ps before next tile overwrites
    }

    // ---- normalize + store (tf32-rounded; feeds O-proj GEMM A) ----
    float inv0 = 1.0f / l0, inv1 = 1.0f / l1;
    int gr0 = i0 + r_w + gid, gr1 = gr0 + 8;
    #pragma unroll
    for (int nf = 0; nf < 8; nf++) {
        int col = zh*HD_ + nf*8 + tg*2;
        if (gr0 < N_)
            *reinterpret_cast<float2*>(o + (size_t)(zb*N_ + gr0)*D_ + col) =
                make_float2(rtf(oa[nf][0]*inv0), rtf(oa[nf][1]*inv0));
        if (gr1 < N_)
            *reinterpret_cast<float2*>(o + (size_t)(zb*N_ + gr1)*D_ + col) =
                make_float2(rtf(oa[nf][2]*inv1), rtf(oa[nf][3]*inv1));
    }
}

// ===== Head =====
__global__ void head_kernel(const float* __restrict__ y, const float* __restrict__ hw,
                            const float* __restrict__ hb, float* __restrict__ out) {
    __shared__ float rowv[D_];
    int b = blockIdx.x;
    int tid = threadIdx.x;
    for (int c = tid; c < D_; c += 256) rowv[c] = y[((size_t)(b*N_))*D_ + c];
    __syncthreads();
    for (int c = tid; c < NCLS_; c += 256) {
        float s = hb[c];
        for (int d = 0; d < D_; d++) s = fmaf(rowv[d], hw[(size_t)d*NCLS_ + c], s);
        out[b*NCLS_ + c] = s;
    }
}

extern "C" void kernel_launch(void* const* d_in, const int* in_sizes, int n_in,
                              void* d_out, int out_size) {
    (void)in_sizes; (void)n_in; (void)out_size;
    const float* x       = (const float*)d_in[0];
    const float* proj_w  = (const float*)d_in[1];
    const float* proj_b  = (const float*)d_in[2];
    const float* cls_emb = (const float*)d_in[3];
    const float* pos_emb = (const float*)d_in[4];
    const float* ln1_g   = (const float*)d_in[5];
    const float* ln1_b   = (const float*)d_in[6];
    const float* qw = (const float*)d_in[7];
    const float* qb = (const float*)d_in[8];
    const float* kw = (const float*)d_in[9];
    const float* kb = (const float*)d_in[10];
    const float* vw = (const float*)d_in[11];
    const float* vb = (const float*)d_in[12];
    const float* ow = (const float*)d_in[13];
    const float* ob = (const float*)d_in[14];
    const float* ln2_g = (const float*)d_in[15];
    const float* ln2_b = (const float*)d_in[16];
    const float* fcw = (const float*)d_in[17];
    const float* fcb = (const float*)d_in[18];
    const float* pw  = (const float*)d_in[19];
    const float* pb  = (const float*)d_in[20];
    const float* lnf_g = (const float*)d_in[21];
    const float* lnf_b = (const float*)d_in[22];
    const float* head_w = (const float*)d_in[23];
    const float* head_b = (const float*)d_in[24];
    float* out = (float*)d_out;

    float *t_p, *h_p, *y_p, *qkv_p, *o_p, *m_p;
    float *qkvw, *qkvb, *oww, *fcww, *pww, *projww;
    cudaGetSymbolAddress((void**)&t_p, g_t);
    cudaGetSymbolAddress((void**)&h_p, g_h);
    cudaGetSymbolAddress((void**)&y_p, g_y);
    cudaGetSymbolAddress((void**)&qkv_p, g_qkv);
    cudaGetSymbolAddress((void**)&o_p, g_o);
    cudaGetSymbolAddress((void**)&m_p, g_m);
    cudaGetSymbolAddress((void**)&qkvw, g_qkvw);
    cudaGetSymbolAddress((void**)&qkvb, g_qkvb);
    cudaGetSymbolAddress((void**)&oww, g_oww);
    cudaGetSymbolAddress((void**)&fcww, g_fcww);
    cudaGetSymbolAddress((void**)&pww, g_pww);
    cudaGetSymbolAddress((void**)&projww, g_projww);

    cudaFuncSetAttribute(tf32_gemm<0,0>, cudaFuncAttributeMaxDynamicSharedMemorySize, GA_SMEM);
    cudaFuncSetAttribute(tf32_gemm<0,1>, cudaFuncAttributeMaxDynamicSharedMemorySize, GA_SMEM);
    cudaFuncSetAttribute(tf32_gemm<1,0>, cudaFuncAttributeMaxDynamicSharedMemorySize, GA_SMEM);
    cudaFuncSetAttribute(tf32_gemm<2,1>, cudaFuncAttributeMaxDynamicSharedMemorySize, GA_SMEM);
    cudaFuncSetAttribute(flash_attn, cudaFuncAttributeMaxDynamicSharedMemorySize, FA_SMEM);

    // ---- Weight prep ----
    qkv_concat_w<<<(L_*D_*QD_ + 255)/256, 256>>>(qw, kw, vw, qkvw);
    qkv_concat_b<<<(L_*QD_ + 255)/256, 256>>>(qb, kb, vb, qkvb);
    round_copy<<<(L_*D_*D_ + 255)/256, 256>>>(ow, oww, L_*D_*D_);
    round_copy<<<(L_*D_*MLP_ + 255)/256, 256>>>(fcw, fcww, L_*D_*MLP_);
    round_copy<<<(L_*MLP_*D_ + 255)/256, 256>>>(pw, pww, L_*MLP_*D_);
    round_copy<<<(D_*D_ + 255)/256, 256>>>(proj_w, projww, D_*D_);

    // ---- Patch embed ----
    patchify_kernel<<<(B_*NP_*D_ + 255)/256, 256>>>(x);
    tf32_gemm<0,0><<<dim3(D_/128, PROWS/128), 256, GA_SMEM>>>(
        t_p, projww, proj_b, nullptr, y_p, PROWS, D_, D_);
    assemble_kernel<<<(MROWS*D_ + 255)/256, 256>>>(cls_emb, pos_emb);

    const int gMr = (MROWS + 127) / 128;           // 37
    const dim3 gQKV(QD_/128, gMr);
    const dim3 gD(D_/128, gMr);
    const dim3 gF1(MLP_/128, gMr);
    const dim3 gFA((N_ + 63)/64, B_*NH_);          // 10 x 96
    const int lnB = (MROWS + 7) / 8;

    for (int l = 0; l < L_; l++) {
        float* qkvw_l = qkvw + (size_t)l*D_*QD_;
        float* oww_l  = oww  + (size_t)l*D_*D_;
        float* fcww_l = fcww + (size_t)l*D_*MLP_;
        float* pww_l  = pww  + (size_t)l*MLP_*D_;

        ln_kernel<<<lnB, 256>>>(h_p, y_p, ln1_g + l*D_, ln1_b + l*D_);
        tf32_gemm<0,1><<<gQKV, 256, GA_SMEM>>>(y_p, qkvw_l, qkvb + l*QD_, nullptr,
                                               qkv_p, MROWS, QD_, D_);

        flash_attn<<<gFA, 128, FA_SMEM>>>(qkv_p, o_p);

        tf32_gemm<1,0><<<gD, 256, GA_SMEM>>>(o_p, oww_l, ob + l*D_, h_p, h_p, MROWS, D_, D_);

        ln_kernel<<<lnB, 256>>>(h_p, y_p, ln2_g + l*D_, ln2_b + l*D_);
        tf32_gemm<2,1><<<gF1, 256, GA_SMEM>>>(y_p, fcww_l, fcb + l*MLP_, nullptr,
                                              m_p, MROWS, MLP_, D_);
        tf32_gemm<1,0><<<gD, 256, GA_SMEM>>>(m_p, pww_l, pb + l*D_, h_p, h_p, MROWS, D_, MLP_);
    }

    ln_kernel<<<lnB, 256>>>(h_p, y_p, lnf_g, lnf_b);
    head_kernel<<<B_, 256>>>(y_p, head_w, head_b, out);
}